// round 12
// baseline (speedup 1.0000x reference)
#include <cuda_runtime.h>
#include <cuda_bf16.h>
#include <cstdint>

#define Sd 2048
#define Bd 256
#define Hd 256
#define Pd 3
#define NCTAS 148
#define ITEMS 8192            // 256 b * 32 s-chunks of 64

__device__ float g_hid2[Bd * Hd];
__device__ float g_attn_part[4 * Bd * Sd];   // per-colgroup energy partials
__device__ float g_h1[Bd * Hd];
__device__ float g_scale[Hd];
__device__ float g_shift[Hd];
__device__ float g_gi[Bd * 3 * Hd];
__device__ float g_gh[Bd * 3 * Hd];
__device__ __nv_bfloat16 g_xb[(size_t)Sd * Bd * Hd];   // enc bf16, [b][s][h]

__device__ __forceinline__ float sigmoidf_(float x) {
    return 1.0f / (1.0f + __expf(-x));
}
__device__ __forceinline__ float tanh_ap(float x) {
    float y; asm("tanh.approx.f32 %0, %1;" : "=f"(y) : "f"(x)); return y;
}
__device__ __forceinline__ uint32_t smem_u32f(const void* p) {
    uint32_t a;
    asm("{ .reg .u64 t; cvta.to.shared.u64 t, %1; cvt.u32.u64 %0, t; }" : "=r"(a) : "l"(p));
    return a;
}
__device__ __forceinline__ void ldsm_x4(uint32_t& r0, uint32_t& r1,
                                        uint32_t& r2, uint32_t& r3, uint32_t addr) {
    asm volatile("ldmatrix.sync.aligned.m8n8.x4.shared.b16 {%0,%1,%2,%3}, [%4];"
                 : "=r"(r0), "=r"(r1), "=r"(r2), "=r"(r3) : "r"(addr));
}
__device__ __forceinline__ void mma16816(float* d, uint32_t a0, uint32_t a1,
                                         uint32_t a2, uint32_t a3,
                                         uint32_t b0, uint32_t b1) {
    asm volatile(
        "mma.sync.aligned.m16n8k16.row.col.f32.bf16.bf16.f32 "
        "{%0,%1,%2,%3},{%4,%5,%6,%7},{%8,%9},{%0,%1,%2,%3};"
        : "+f"(d[0]), "+f"(d[1]), "+f"(d[2]), "+f"(d[3])
        : "r"(a0), "r"(a1), "r"(a2), "r"(a3), "r"(b0), "r"(b1));
}
#define CP_ASYNC16(dst, src) \
    asm volatile("cp.async.cg.shared.global [%0], [%1], 16;" :: "r"(dst), "l"(src))
#define CP_COMMIT() asm volatile("cp.async.commit_group;" ::: "memory")
#define CP_WAIT1()  asm volatile("cp.async.wait_group 1;" ::: "memory")

// ---------------- convert: enc fp32 [s][b][h] -> bf16 [b][s][h] -----------
__global__ __launch_bounds__(256)
void convert_kernel(const float* __restrict__ X) {
    int s = blockIdx.x;
    int h8 = (threadIdx.x & 31) * 8;
    int br = threadIdx.x >> 5;
    for (int b = br; b < Bd; b += 8) {
        const float4* src = (const float4*)(X + ((size_t)s * Bd + b) * Hd + h8);
        float4 f0 = __ldcs(src);
        float4 f1 = __ldcs(src + 1);
        __nv_bfloat162 q0 = __floats2bfloat162_rn(f0.x, f0.y);
        __nv_bfloat162 q1 = __floats2bfloat162_rn(f0.z, f0.w);
        __nv_bfloat162 q2 = __floats2bfloat162_rn(f1.x, f1.y);
        __nv_bfloat162 q3 = __floats2bfloat162_rn(f1.z, f1.w);
        uint4 u = { *(uint32_t*)&q0, *(uint32_t*)&q1, *(uint32_t*)&q2, *(uint32_t*)&q3 };
        *(uint4*)(g_xb + ((size_t)b * Sd + s) * Hd + h8) = u;
    }
}

// hid2[b,k] = 0.5*(ldh@Wh^T + bh + be)
__global__ void hid2_kernel(const float* __restrict__ ldh, const float* __restrict__ Wh,
                            const float* __restrict__ bh, const float* __restrict__ be) {
    int b = blockIdx.x, tid = threadIdx.x, lane = tid & 31, warp = tid >> 5;
    __shared__ float hsm[Hd];
    hsm[tid] = ldh[b * Hd + tid];
    __syncthreads();
    for (int k = warp; k < Hd; k += 8) {
        float a = 0.f;
        #pragma unroll
        for (int t = 0; t < 8; t++) a += hsm[lane + 32 * t] * Wh[k * Hd + lane + 32 * t];
        #pragma unroll
        for (int o = 16; o; o >>= 1) a += __shfl_xor_sync(0xffffffffu, a, o);
        if (lane == 0) g_hid2[b * Hd + k] = 0.5f * (a + bh[k] + be[k]);
    }
}

// ---------------- persistent HMMA energy kernel (cp.async pipeline) -------
// part[cg][b][s] = sum_{c in cg*64..+63} wv2[c]*tanh(0.5*(X@We^T)[m,c]+hid2[b,c])
#define WST 264
#define OFF_WE 0
#define SZ_WE (256 * WST * 2)                // 135168
#define OFF_X0 SZ_WE
#define SZ_X (64 * WST * 2)                  // 33792
#define OFF_X1 (OFF_X0 + SZ_X)
#define OFF_WV (OFF_X1 + SZ_X)               // 202752
#define ESMEM (OFF_WV + 1024)                // 203776

__global__ __launch_bounds__(256, 1)
void energy_hmma_kernel(const float* __restrict__ We,
                        const float* __restrict__ Wv) {
    extern __shared__ char smem[];
    const uint32_t sm32 = smem_u32f(smem);
    const int tid = threadIdx.x, lane = tid & 31, wid = tid >> 5;
    float* wv2s = (float*)(smem + OFF_WV);

    // stage We (row n = tid) as bf16 [n][k] stride 264, once
    {
        const float2* wr = (const float2*)(We + tid * Hd);
        __nv_bfloat16* wd = (__nv_bfloat16*)(smem + OFF_WE) + tid * WST;
        #pragma unroll 8
        for (int j = 0; j < 128; j++) {
            float2 v = wr[j];
            __nv_bfloat162 p = __floats2bfloat162_rn(v.x, v.y);
            *(uint32_t*)(wd + 2 * j) = *(uint32_t*)&p;
        }
    }
    wv2s[tid] = 0.5f * Wv[tid];

    const int start = (ITEMS * blockIdx.x) / NCTAS;
    const int n = (ITEMS * (blockIdx.x + 1)) / NCTAS - start;

    // cp.async issue: item i -> buf[i&1]; source is contiguous 32KB in g_xb
    auto issue = [&](int i) {
        int item = start + i;
        int bb = item >> 5, s0 = (item & 31) << 6;
        const char* src = (const char*)(g_xb + ((size_t)bb * Sd + s0) * Hd);
        uint32_t dstb = sm32 + ((i & 1) ? OFF_X1 : OFF_X0);
        #pragma unroll
        for (int k = 0; k < 8; k++) {
            int c = tid + k * 256;                 // chunk id: row=c>>5, j=c&31
            uint32_t dst = dstb + (uint32_t)(c >> 5) * (WST * 2) + (uint32_t)(c & 31) * 16;
            CP_ASYNC16(dst, src + (size_t)c * 16);
        }
    };

    issue(0); CP_COMMIT();
    __syncthreads();   // We + wv2 visible

    const int rg = wid & 1, cg = wid >> 1;
    const int r0 = rg * 32, c0 = cg * 64;
    const uint32_t a_rel = (uint32_t)((r0 + (lane & 15)) * WST + (lane >> 4) * 8) * 2;
    const uint32_t b_base = sm32 + OFF_WE
        + (uint32_t)((c0 + (lane & 7) + ((lane >> 4) << 3)) * WST + ((lane >> 3) & 1) * 8) * 2;

    for (int i = 0; i < n; i++) {
        const int item = start + i;
        const int bb = item >> 5, s0 = (item & 31) << 6;

        if (i + 1 < n) issue(i + 1);     // buf[(i+1)&1] freed at end of iter i-1
        CP_COMMIT();
        CP_WAIT1();
        __syncthreads();   // buf[i&1] filled, visible to all warps

        const uint32_t xb = sm32 + ((i & 1) ? OFF_X1 : OFF_X0);
        float d[2][8][4];
        #pragma unroll
        for (int mt = 0; mt < 2; mt++)
            #pragma unroll
            for (int nt = 0; nt < 8; nt++)
                #pragma unroll
                for (int j = 0; j < 4; j++) d[mt][nt][j] = 0.f;

        const uint32_t abase = xb + a_rel;
        #pragma unroll 4
        for (int ks = 0; ks < 16; ks++) {
            uint32_t a0[4], a1[4];
            ldsm_x4(a0[0], a0[1], a0[2], a0[3], abase + ks * 32);
            ldsm_x4(a1[0], a1[1], a1[2], a1[3], abase + 16 * WST * 2 + ks * 32);
            #pragma unroll
            for (int np = 0; np < 4; np++) {
                uint32_t b0, b1, b2, b3;
                ldsm_x4(b0, b1, b2, b3, b_base + (uint32_t)(np * 16 * WST) * 2 + ks * 32);
                mma16816(d[0][2 * np],     a0[0], a0[1], a0[2], a0[3], b0, b1);
                mma16816(d[0][2 * np + 1], a0[0], a0[1], a0[2], a0[3], b2, b3);
                mma16816(d[1][2 * np],     a1[0], a1[1], a1[2], a1[3], b0, b1);
                mma16816(d[1][2 * np + 1], a1[0], a1[1], a1[2], a1[3], b2, b3);
            }
        }
        __syncthreads();   // all warps done reading buf[i&1]; it may be refilled

        // epilogue AFTER the release sync: overlaps other warps' next-item MMA
        {
            const float* h2 = g_hid2 + bb * Hd;
            float p[4] = {0.f, 0.f, 0.f, 0.f};
            #pragma unroll
            for (int nt = 0; nt < 8; nt++) {
                int col = c0 + nt * 8 + (lane & 3) * 2;
                float w0 = wv2s[col], w1 = wv2s[col + 1];
                float h0 = __ldg(h2 + col), h1 = __ldg(h2 + col + 1);
                #pragma unroll
                for (int mt = 0; mt < 2; mt++) {
                    p[mt * 2 + 0] += w0 * tanh_ap(fmaf(0.5f, d[mt][nt][0], h0))
                                   + w1 * tanh_ap(fmaf(0.5f, d[mt][nt][1], h1));
                    p[mt * 2 + 1] += w0 * tanh_ap(fmaf(0.5f, d[mt][nt][2], h0))
                                   + w1 * tanh_ap(fmaf(0.5f, d[mt][nt][3], h1));
                }
            }
            #pragma unroll
            for (int j = 0; j < 4; j++) {
                p[j] += __shfl_xor_sync(0xffffffffu, p[j], 1);
                p[j] += __shfl_xor_sync(0xffffffffu, p[j], 2);
            }
            if ((lane & 3) == 0) {
                int q = lane >> 2;
                size_t base = (size_t)cg * (Bd * Sd) + (size_t)bb * Sd + s0 + r0 + q;
                g_attn_part[base]      = p[0];
                g_attn_part[base + 8]  = p[1];
                g_attn_part[base + 16] = p[2];
                g_attn_part[base + 24] = p[3];
            }
        }
    }
}

// ---------------- softmax over s, per b (sums 4 partial slices) -----------
__global__ void softmax_kernel(float* __restrict__ attn) {
    int b = blockIdx.x, tid = threadIdx.x;
    const size_t sl = (size_t)Bd * Sd;
    float* row = attn + b * Sd;
    float v[8]; float mx = -1e30f;
    #pragma unroll
    for (int t = 0; t < 8; t++) {
        size_t idx = (size_t)b * Sd + tid + 256 * t;
        v[t] = g_attn_part[idx] + g_attn_part[sl + idx]
             + g_attn_part[2 * sl + idx] + g_attn_part[3 * sl + idx];
        mx = fmaxf(mx, v[t]);
    }
    __shared__ float redm[8]; __shared__ float reds[8];
    #pragma unroll
    for (int o = 16; o; o >>= 1) mx = fmaxf(mx, __shfl_xor_sync(0xffffffffu, mx, o));
    if ((tid & 31) == 0) redm[tid >> 5] = mx;
    __syncthreads();
    mx = redm[0];
    #pragma unroll
    for (int i = 1; i < 8; i++) mx = fmaxf(mx, redm[i]);
    float sum = 0.f;
    #pragma unroll
    for (int t = 0; t < 8; t++) { v[t] = __expf(v[t] - mx); sum += v[t]; }
    #pragma unroll
    for (int o = 16; o; o >>= 1) sum += __shfl_xor_sync(0xffffffffu, sum, o);
    if ((tid & 31) == 0) reds[tid >> 5] = sum;
    __syncthreads();
    sum = 0.f;
    #pragma unroll
    for (int i = 0; i < 8; i++) sum += reds[i];
    float inv = 1.f / sum;
    #pragma unroll
    for (int t = 0; t < 8; t++) row[tid + 256 * t] = v[t] * inv;
}

// ---------------- context: zero + streamed fp32 partials via atomics ------
__global__ void zero_ctx_kernel(float* __restrict__ out_ctx) {
    out_ctx[blockIdx.x * 256 + threadIdx.x] = 0.f;
}

__global__ void ctx_part_kernel(const float* __restrict__ enc,
                                const float* __restrict__ attn,
                                float* __restrict__ out_ctx) {
    int b = blockIdx.x, sc = blockIdx.y, h = threadIdx.x;
    int s0 = sc * 256;
    const float* wrow = attn + b * Sd + s0;
    const float* e = enc + ((size_t)s0 * Bd + b) * Hd + h;
    float a0 = 0.f, a1 = 0.f, a2 = 0.f, a3 = 0.f;
    #pragma unroll 2
    for (int s = 0; s < 256; s += 4) {
        a0 += wrow[s + 0] * __ldcs(e + (size_t)(s + 0) * (Bd * Hd));
        a1 += wrow[s + 1] * __ldcs(e + (size_t)(s + 1) * (Bd * Hd));
        a2 += wrow[s + 2] * __ldcs(e + (size_t)(s + 2) * (Bd * Hd));
        a3 += wrow[s + 3] * __ldcs(e + (size_t)(s + 3) * (Bd * Hd));
    }
    atomicAdd(&out_ctx[b * Hd + h], (a0 + a1) + (a2 + a3));
}

// ---------------- GRU: weight-stationary gate GEMM ------------------------
__global__ __launch_bounds__(256)
void gru_gemm_kernel(const float* __restrict__ last_palette,
                     const float* __restrict__ ldh, const float* __restrict__ ctx,
                     const float* __restrict__ W_ih, const float* __restrict__ W_hh) {
    __shared__ float Wi[8][260];
    __shared__ float Whh[8][256];
    const int tid = threadIdx.x, lane = tid & 31, warp = tid >> 5;
    const int k0 = blockIdx.x * 8;
    const int KX = Hd + Pd;   // 259
    for (int idx = tid; idx < 8 * KX; idx += 256)
        Wi[idx / KX][idx % KX] = W_ih[(size_t)(k0 + idx / KX) * KX + idx % KX];
    for (int idx = tid; idx < 8 * Hd; idx += 256)
        Whh[idx >> 8][idx & 255] = W_hh[(size_t)(k0 + (idx >> 8)) * Hd + (idx & 255)];
    __syncthreads();

    for (int it = 0; it < 32; it++) {
        int b = warp + 8 * it;
        float xr[8], hr[8];
        #pragma unroll
        for (int t = 0; t < 8; t++) {
            int j = lane + 32 * t;
            xr[t] = (j < 3) ? last_palette[b * Pd + j] : ctx[b * Hd + (j - 3)];
            hr[t] = ldh[b * Hd + j];
        }
        float xe = (lane < 3) ? ctx[b * Hd + 253 + lane] : 0.f;
        #pragma unroll
        for (int o = 0; o < 8; o++) {
            float a = (lane < 3) ? xe * Wi[o][256 + lane] : 0.f;
            float c = 0.f;
            #pragma unroll
            for (int t = 0; t < 8; t++) {
                a += xr[t] * Wi[o][lane + 32 * t];
                c += hr[t] * Whh[o][lane + 32 * t];
            }
            #pragma unroll
            for (int off = 16; off; off >>= 1) {
                a += __shfl_xor_sync(0xffffffffu, a, off);
                c += __shfl_xor_sync(0xffffffffu, c, off);
            }
            if (lane == 0) {
                g_gi[(size_t)b * (3 * Hd) + k0 + o] = a;
                g_gh[(size_t)b * (3 * Hd) + k0 + o] = c;
            }
        }
    }
}

// ---------------- GRU combine + h1 (fused, per-b block) -------------------
__global__ void gru_h1_kernel(const float* __restrict__ ldh,
                              const float* __restrict__ b_ih,
                              const float* __restrict__ b_hh,
                              const float* __restrict__ W1,
                              const float* __restrict__ b1,
                              float* __restrict__ out_gru) {
    int b = blockIdx.x, tid = threadIdx.x, lane = tid & 31, warp = tid >> 5;
    __shared__ float gs[Hd];
    {
        int k = tid;
        const float* gi = g_gi + (size_t)b * (3 * Hd);
        const float* gh = g_gh + (size_t)b * (3 * Hd);
        float r = sigmoidf_(gi[k] + b_ih[k] + gh[k] + b_hh[k]);
        float z = sigmoidf_(gi[Hd + k] + b_ih[Hd + k] + gh[Hd + k] + b_hh[Hd + k]);
        float nn = tanhf(gi[2 * Hd + k] + b_ih[2 * Hd + k]
                         + r * (gh[2 * Hd + k] + b_hh[2 * Hd + k]));
        float g = (1.f - z) * nn + z * ldh[b * Hd + k];
        out_gru[b * Hd + k] = g;
        gs[k] = g;
    }
    __syncthreads();
    for (int k = warp; k < Hd; k += 8) {
        float a = 0.f;
        #pragma unroll
        for (int t = 0; t < 8; t++) a += gs[lane + 32 * t] * W1[k * Hd + lane + 32 * t];
        #pragma unroll
        for (int o = 16; o; o >>= 1) a += __shfl_xor_sync(0xffffffffu, a, o);
        if (lane == 0) g_h1[b * Hd + k] = fmaxf(a + b1[k], 0.f);
    }
}

// ---------------- BatchNorm stats, parallel (16 blocks) --------------------
__global__ void bn_kernel(const float* __restrict__ gamma, const float* __restrict__ beta) {
    __shared__ float ps[16][16];
    __shared__ float pq[16][16];
    int tid = threadIdx.x;
    int kl = tid & 15, bl = tid >> 4;
    int k = blockIdx.x * 16 + kl;
    float s = 0.f, sq = 0.f;
    #pragma unroll
    for (int j = 0; j < 16; j++) {
        float v = g_h1[(bl + 16 * j) * Hd + k];
        s += v; sq += v * v;
    }
    ps[bl][kl] = s; pq[bl][kl] = sq;
    __syncthreads();
    if (tid < 16) {
        float ts = 0.f, tq = 0.f;
        #pragma unroll
        for (int j = 0; j < 16; j++) { ts += ps[j][tid]; tq += pq[j][tid]; }
        int kk = blockIdx.x * 16 + tid;
        float mu = ts * (1.f / Bd);
        float var = tq * (1.f / Bd) - mu * mu;
        float sc = rsqrtf(var + 1e-5f) * gamma[kk];
        g_scale[kk] = sc; g_shift[kk] = beta[kk] - mu * sc;
    }
}

__global__ void palette_kernel(const float* __restrict__ W2, const float* __restrict__ b2,
                               float* __restrict__ out_pal) {
    int b = blockIdx.x, lane = threadIdx.x & 31, p = threadIdx.x >> 5;
    if (p >= Pd) return;
    float a = 0.f;
    #pragma unroll
    for (int t = 0; t < 8; t++) {
        int h = lane + 32 * t;
        a += (g_h1[b * Hd + h] * g_scale[h] + g_shift[h]) * W2[p * Hd + h];
    }
    #pragma unroll
    for (int o = 16; o; o >>= 1) a += __shfl_xor_sync(0xffffffffu, a, o);
    if (lane == 0) out_pal[b * Pd + p] = a + b2[p];
}

extern "C" void kernel_launch(void* const* d_in, const int* in_sizes, int n_in,
                              void* d_out, int out_size) {
    const float* last_palette = (const float*)d_in[0];
    const float* ldh          = (const float*)d_in[1];
    const float* enc          = (const float*)d_in[2];
    const float* We           = (const float*)d_in[3];
    const float* be           = (const float*)d_in[4];
    const float* Wh           = (const float*)d_in[5];
    const float* bh           = (const float*)d_in[6];
    const float* Wv           = (const float*)d_in[7];
    const float* W_ih         = (const float*)d_in[9];
    const float* b_ih         = (const float*)d_in[10];
    const float* W_hh         = (const float*)d_in[11];
    const float* b_hh         = (const float*)d_in[12];
    const float* W1           = (const float*)d_in[13];
    const float* b1           = (const float*)d_in[14];
    const float* gamma        = (const float*)d_in[15];
    const float* beta         = (const float*)d_in[16];
    const float* W2           = (const float*)d_in[17];
    const float* b2           = (const float*)d_in[18];

    float* out      = (float*)d_out;
    float* out_pal  = out;
    float* out_ctx  = out + Bd * Pd;
    float* out_gru  = out + Bd * Pd + Bd * Hd;
    float* out_attn = out + Bd * Pd + 2 * Bd * Hd;

    static bool attr_done = false;
    if (!attr_done) {
        cudaFuncSetAttribute(energy_hmma_kernel,
                             cudaFuncAttributeMaxDynamicSharedMemorySize, ESMEM);
        attr_done = true;
    }

    convert_kernel<<<Sd, 256>>>(enc);
    hid2_kernel<<<Bd, 256>>>(ldh, Wh, bh, be);
    energy_hmma_kernel<<<NCTAS, 256, ESMEM>>>(We, Wv);
    softmax_kernel<<<Bd, 256>>>(out_attn);
    zero_ctx_kernel<<<Bd, 256>>>(out_ctx);
    ctx_part_kernel<<<dim3(Bd, 8), 256>>>(enc, out_attn, out_ctx);
    gru_gemm_kernel<<<96, 256>>>(last_palette, ldh, out_ctx, W_ih, W_hh);
    gru_h1_kernel<<<Bd, 256>>>(ldh, b_ih, b_hh, W1, b1, out_gru);
    bn_kernel<<<16, 256>>>(gamma, beta);
    palette_kernel<<<Bd, 128>>>(W2, b2, out_pal);
}

// round 13
// speedup vs baseline: 1.1312x; 1.1312x over previous
#include <cuda_runtime.h>
#include <cuda_bf16.h>
#include <cstdint>

#define Sd 2048
#define Bd 256
#define Hd 256
#define Pd 3
#define NCTAS 148
#define ITEMS 16384           // 256 b * 64 s-chunks of 32

__device__ float g_hid2[Bd * Hd];
__device__ float g_attn_part[4 * Bd * Sd];   // per-colgroup energy partials
__device__ float g_h1[Bd * Hd];
__device__ float g_scale[Hd];
__device__ float g_shift[Hd];
__device__ float g_gi[Bd * 3 * Hd];
__device__ float g_gh[Bd * 3 * Hd];

__device__ __forceinline__ float sigmoidf_(float x) {
    return 1.0f / (1.0f + __expf(-x));
}
__device__ __forceinline__ float tanh_ap(float x) {
    float y; asm("tanh.approx.f32 %0, %1;" : "=f"(y) : "f"(x)); return y;
}
__device__ __forceinline__ uint32_t smem_u32f(const void* p) {
    uint32_t a;
    asm("{ .reg .u64 t; cvta.to.shared.u64 t, %1; cvt.u32.u64 %0, t; }" : "=r"(a) : "l"(p));
    return a;
}
__device__ __forceinline__ void ldsm_x4(uint32_t& r0, uint32_t& r1,
                                        uint32_t& r2, uint32_t& r3, uint32_t addr) {
    asm volatile("ldmatrix.sync.aligned.m8n8.x4.shared.b16 {%0,%1,%2,%3}, [%4];"
                 : "=r"(r0), "=r"(r1), "=r"(r2), "=r"(r3) : "r"(addr));
}
__device__ __forceinline__ void mma16816(float* d, uint32_t a0, uint32_t a1,
                                         uint32_t a2, uint32_t a3,
                                         uint32_t b0, uint32_t b1) {
    asm volatile(
        "mma.sync.aligned.m16n8k16.row.col.f32.bf16.bf16.f32 "
        "{%0,%1,%2,%3},{%4,%5,%6,%7},{%8,%9},{%0,%1,%2,%3};"
        : "+f"(d[0]), "+f"(d[1]), "+f"(d[2]), "+f"(d[3])
        : "r"(a0), "r"(a1), "r"(a2), "r"(a3), "r"(b0), "r"(b1));
}
#define CP_ASYNC16(dst, src) \
    asm volatile("cp.async.cg.shared.global [%0], [%1], 16;" :: "r"(dst), "l"(src))
#define CP_COMMIT() asm volatile("cp.async.commit_group;" ::: "memory")
#define CP_WAIT0()  asm volatile("cp.async.wait_group 0;" ::: "memory")

// hid2[b,k] = 0.5*(ldh@Wh^T + bh + be)
__global__ void hid2_kernel(const float* __restrict__ ldh, const float* __restrict__ Wh,
                            const float* __restrict__ bh, const float* __restrict__ be) {
    int b = blockIdx.x, tid = threadIdx.x, lane = tid & 31, warp = tid >> 5;
    __shared__ float hsm[Hd];
    hsm[tid] = ldh[b * Hd + tid];
    __syncthreads();
    for (int k = warp; k < Hd; k += 8) {
        float a = 0.f;
        #pragma unroll
        for (int t = 0; t < 8; t++) a += hsm[lane + 32 * t] * Wh[k * Hd + lane + 32 * t];
        #pragma unroll
        for (int o = 16; o; o >>= 1) a += __shfl_xor_sync(0xffffffffu, a, o);
        if (lane == 0) g_hid2[b * Hd + k] = 0.5f * (a + bh[k] + be[k]);
    }
}

// ---------------- persistent HMMA energy kernel, fused fp32 ingest --------
// part[cg][b][s] = sum_{c in cg*64..+63} wv2[c]*tanh(0.5*(X@We^T)[m,c]+hid2[b,c])
// Per 32-row item: cp.async fp32 rows -> linear smem stage (thread-owned
// chunks), same-thread LDS/cvt/STS into double-buffered bf16 tile, MMA.
#define WST 264
#define OFF_WE 0
#define SZ_WE (256 * WST * 2)                // 135168
#define OFF_ST SZ_WE                         // fp32 stage, linear 32KB
#define SZ_ST 32768
#define OFF_X0 (OFF_ST + SZ_ST)              // 167936
#define SZ_X (32 * WST * 2)                  // 16896
#define OFF_X1 (OFF_X0 + SZ_X)               // 184832
#define OFF_WV (OFF_X1 + SZ_X)               // 201728
#define ESMEM (OFF_WV + 1024)                // 202752

__global__ __launch_bounds__(256, 1)
void energy_hmma_kernel(const float* __restrict__ X, const float* __restrict__ We,
                        const float* __restrict__ Wv) {
    extern __shared__ char smem[];
    const uint32_t sm32 = smem_u32f(smem);
    const int tid = threadIdx.x, lane = tid & 31, wid = tid >> 5;
    float* wv2s = (float*)(smem + OFF_WV);

    // stage We (row n = tid) as bf16 [n][k] stride 264, once
    {
        const float2* wr = (const float2*)(We + tid * Hd);
        __nv_bfloat16* wd = (__nv_bfloat16*)(smem + OFF_WE) + tid * WST;
        #pragma unroll 8
        for (int j = 0; j < 128; j++) {
            float2 v = wr[j];
            __nv_bfloat162 p = __floats2bfloat162_rn(v.x, v.y);
            *(uint32_t*)(wd + 2 * j) = *(uint32_t*)&p;
        }
    }
    wv2s[tid] = 0.5f * Wv[tid];

    const int start = (ITEMS * blockIdx.x) / NCTAS;
    const int n = (ITEMS * (blockIdx.x + 1)) / NCTAS - start;

    // cp.async fp32 rows of item i into the linear stage (thread-owned chunks)
    auto issue = [&](int i) {
        int item = start + i;
        int bb = item >> 6, s0 = (item & 63) << 5;
        #pragma unroll
        for (int k = 0; k < 8; k++) {
            int c = tid + k * 256;                 // float4 index 0..2047
            int row = c >> 6, col16 = c & 63;
            const char* src = (const char*)(X + ((size_t)(s0 + row) * Bd + bb) * Hd)
                            + col16 * 16;
            CP_ASYNC16(sm32 + OFF_ST + (uint32_t)c * 16, src);
        }
    };
    // convert own stage chunks -> bf16 tile buf (no barrier needed: own data)
    auto convert = [&](int buf) {
        const float4* st = (const float4*)(smem + OFF_ST);
        __nv_bfloat16* xd = (__nv_bfloat16*)(smem + (buf ? OFF_X1 : OFF_X0));
        #pragma unroll
        for (int j = 0; j < 8; j++) {
            int q = tid + 256 * j;                 // float4 index
            float4 f = st[q];
            int row = q >> 6, c4 = q & 63;
            __nv_bfloat162 a = __floats2bfloat162_rn(f.x, f.y);
            __nv_bfloat162 b = __floats2bfloat162_rn(f.z, f.w);
            uint2 u = { *(uint32_t*)&a, *(uint32_t*)&b };
            *(uint2*)(xd + row * WST + c4 * 4) = u;
        }
    };

    // prologue: item 0 -> xb0; prefetch item 1 into stage
    issue(0); CP_COMMIT();
    CP_WAIT0();
    convert(0);
    if (n > 1) { issue(1); CP_COMMIT(); }
    __syncthreads();   // We, wv2, xb0 visible

    const int rg = wid & 1, cg = wid >> 1;
    const int r0 = rg * 16, c0 = cg * 64;
    const uint32_t a_rel = (uint32_t)((r0 + (lane & 15)) * WST + (lane >> 4) * 8) * 2;
    const uint32_t b_base = sm32 + OFF_WE
        + (uint32_t)((c0 + (lane & 7) + ((lane >> 4) << 3)) * WST + ((lane >> 3) & 1) * 8) * 2;

    for (int i = 0; i < n; i++) {
        const int item = start + i;
        const int bb = item >> 6, s0 = (item & 63) << 5;

        // MMA: 16 rows x 64 cols x k256 per warp on xb[i&1]
        float d[8][4];
        #pragma unroll
        for (int nt = 0; nt < 8; nt++)
            #pragma unroll
            for (int j = 0; j < 4; j++) d[nt][j] = 0.f;

        const uint32_t abase = sm32 + ((i & 1) ? OFF_X1 : OFF_X0) + a_rel;
        #pragma unroll 4
        for (int ks = 0; ks < 16; ks++) {
            uint32_t a0, a1, a2, a3;
            ldsm_x4(a0, a1, a2, a3, abase + ks * 32);
            #pragma unroll
            for (int np = 0; np < 4; np++) {
                uint32_t b0, b1, b2, b3;
                ldsm_x4(b0, b1, b2, b3, b_base + (uint32_t)(np * 16 * WST) * 2 + ks * 32);
                mma16816(d[2 * np],     a0, a1, a2, a3, b0, b1);
                mma16816(d[2 * np + 1], a0, a1, a2, a3, b2, b3);
            }
        }

        // pipeline: finish item i+1's DRAM load, convert it, prefetch i+2
        if (i + 1 < n) {
            CP_WAIT0();
            convert((i + 1) & 1);
            if (i + 2 < n) { issue(i + 2); CP_COMMIT(); }
        }
        __syncthreads();   // xb[(i+1)&1] ready; all warps done with xb[i&1]

        // epilogue after sync: tanh + Wv dot -> g_attn_part[cg]
        {
            const float* h2 = g_hid2 + bb * Hd;
            float p0 = 0.f, p1 = 0.f;
            #pragma unroll
            for (int nt = 0; nt < 8; nt++) {
                int col = c0 + nt * 8 + (lane & 3) * 2;
                float w0 = wv2s[col], w1 = wv2s[col + 1];
                float h0 = __ldg(h2 + col), h1 = __ldg(h2 + col + 1);
                p0 += w0 * tanh_ap(fmaf(0.5f, d[nt][0], h0))
                    + w1 * tanh_ap(fmaf(0.5f, d[nt][1], h1));
                p1 += w0 * tanh_ap(fmaf(0.5f, d[nt][2], h0))
                    + w1 * tanh_ap(fmaf(0.5f, d[nt][3], h1));
            }
            p0 += __shfl_xor_sync(0xffffffffu, p0, 1);
            p0 += __shfl_xor_sync(0xffffffffu, p0, 2);
            p1 += __shfl_xor_sync(0xffffffffu, p1, 1);
            p1 += __shfl_xor_sync(0xffffffffu, p1, 2);
            if ((lane & 3) == 0) {
                int q = lane >> 2;
                size_t base = (size_t)cg * (Bd * Sd) + (size_t)bb * Sd + s0 + r0 + q;
                g_attn_part[base] = p0;
                g_attn_part[base + 8] = p1;
            }
        }
    }
}

// ---------------- softmax over s, per b (sums 4 partial slices) -----------
__global__ void softmax_kernel(float* __restrict__ attn) {
    int b = blockIdx.x, tid = threadIdx.x;
    const size_t sl = (size_t)Bd * Sd;
    float* row = attn + b * Sd;
    float v[8]; float mx = -1e30f;
    #pragma unroll
    for (int t = 0; t < 8; t++) {
        size_t idx = (size_t)b * Sd + tid + 256 * t;
        v[t] = g_attn_part[idx] + g_attn_part[sl + idx]
             + g_attn_part[2 * sl + idx] + g_attn_part[3 * sl + idx];
        mx = fmaxf(mx, v[t]);
    }
    __shared__ float redm[8]; __shared__ float reds[8];
    #pragma unroll
    for (int o = 16; o; o >>= 1) mx = fmaxf(mx, __shfl_xor_sync(0xffffffffu, mx, o));
    if ((tid & 31) == 0) redm[tid >> 5] = mx;
    __syncthreads();
    mx = redm[0];
    #pragma unroll
    for (int i = 1; i < 8; i++) mx = fmaxf(mx, redm[i]);
    float sum = 0.f;
    #pragma unroll
    for (int t = 0; t < 8; t++) { v[t] = __expf(v[t] - mx); sum += v[t]; }
    #pragma unroll
    for (int o = 16; o; o >>= 1) sum += __shfl_xor_sync(0xffffffffu, sum, o);
    if ((tid & 31) == 0) reds[tid >> 5] = sum;
    __syncthreads();
    sum = 0.f;
    #pragma unroll
    for (int i = 0; i < 8; i++) sum += reds[i];
    float inv = 1.f / sum;
    #pragma unroll
    for (int t = 0; t < 8; t++) row[tid + 256 * t] = v[t] * inv;
}

// ---------------- context: zero + streamed fp32 partials via atomics ------
__global__ void zero_ctx_kernel(float* __restrict__ out_ctx) {
    out_ctx[blockIdx.x * 256 + threadIdx.x] = 0.f;
}

__global__ void ctx_part_kernel(const float* __restrict__ enc,
                                const float* __restrict__ attn,
                                float* __restrict__ out_ctx) {
    int b = blockIdx.x, sc = blockIdx.y, h = threadIdx.x;
    int s0 = sc * 256;
    const float* wrow = attn + b * Sd + s0;
    const float* e = enc + ((size_t)s0 * Bd + b) * Hd + h;
    float a0 = 0.f, a1 = 0.f, a2 = 0.f, a3 = 0.f;
    #pragma unroll 2
    for (int s = 0; s < 256; s += 4) {
        a0 += wrow[s + 0] * __ldcs(e + (size_t)(s + 0) * (Bd * Hd));
        a1 += wrow[s + 1] * __ldcs(e + (size_t)(s + 1) * (Bd * Hd));
        a2 += wrow[s + 2] * __ldcs(e + (size_t)(s + 2) * (Bd * Hd));
        a3 += wrow[s + 3] * __ldcs(e + (size_t)(s + 3) * (Bd * Hd));
    }
    atomicAdd(&out_ctx[b * Hd + h], (a0 + a1) + (a2 + a3));
}

// ---------------- GRU: weight-stationary gate GEMM ------------------------
__global__ __launch_bounds__(256)
void gru_gemm_kernel(const float* __restrict__ last_palette,
                     const float* __restrict__ ldh, const float* __restrict__ ctx,
                     const float* __restrict__ W_ih, const float* __restrict__ W_hh) {
    __shared__ float Wi[8][260];
    __shared__ float Whh[8][256];
    const int tid = threadIdx.x, lane = tid & 31, warp = tid >> 5;
    const int k0 = blockIdx.x * 8;
    const int KX = Hd + Pd;   // 259
    for (int idx = tid; idx < 8 * KX; idx += 256)
        Wi[idx / KX][idx % KX] = W_ih[(size_t)(k0 + idx / KX) * KX + idx % KX];
    for (int idx = tid; idx < 8 * Hd; idx += 256)
        Whh[idx >> 8][idx & 255] = W_hh[(size_t)(k0 + (idx >> 8)) * Hd + (idx & 255)];
    __syncthreads();

    for (int it = 0; it < 32; it++) {
        int b = warp + 8 * it;
        float xr[8], hr[8];
        #pragma unroll
        for (int t = 0; t < 8; t++) {
            int j = lane + 32 * t;
            xr[t] = (j < 3) ? last_palette[b * Pd + j] : ctx[b * Hd + (j - 3)];
            hr[t] = ldh[b * Hd + j];
        }
        float xe = (lane < 3) ? ctx[b * Hd + 253 + lane] : 0.f;
        #pragma unroll
        for (int o = 0; o < 8; o++) {
            float a = (lane < 3) ? xe * Wi[o][256 + lane] : 0.f;
            float c = 0.f;
            #pragma unroll
            for (int t = 0; t < 8; t++) {
                a += xr[t] * Wi[o][lane + 32 * t];
                c += hr[t] * Whh[o][lane + 32 * t];
            }
            #pragma unroll
            for (int off = 16; off; off >>= 1) {
                a += __shfl_xor_sync(0xffffffffu, a, off);
                c += __shfl_xor_sync(0xffffffffu, c, off);
            }
            if (lane == 0) {
                g_gi[(size_t)b * (3 * Hd) + k0 + o] = a;
                g_gh[(size_t)b * (3 * Hd) + k0 + o] = c;
            }
        }
    }
}

// ---------------- GRU combine + h1 (fused, per-b block) -------------------
__global__ void gru_h1_kernel(const float* __restrict__ ldh,
                              const float* __restrict__ b_ih,
                              const float* __restrict__ b_hh,
                              const float* __restrict__ W1,
                              const float* __restrict__ b1,
                              float* __restrict__ out_gru) {
    int b = blockIdx.x, tid = threadIdx.x, lane = tid & 31, warp = tid >> 5;
    __shared__ float gs[Hd];
    {
        int k = tid;
        const float* gi = g_gi + (size_t)b * (3 * Hd);
        const float* gh = g_gh + (size_t)b * (3 * Hd);
        float r = sigmoidf_(gi[k] + b_ih[k] + gh[k] + b_hh[k]);
        float z = sigmoidf_(gi[Hd + k] + b_ih[Hd + k] + gh[Hd + k] + b_hh[Hd + k]);
        float nn = tanhf(gi[2 * Hd + k] + b_ih[2 * Hd + k]
                         + r * (gh[2 * Hd + k] + b_hh[2 * Hd + k]));
        float g = (1.f - z) * nn + z * ldh[b * Hd + k];
        out_gru[b * Hd + k] = g;
        gs[k] = g;
    }
    __syncthreads();
    for (int k = warp; k < Hd; k += 8) {
        float a = 0.f;
        #pragma unroll
        for (int t = 0; t < 8; t++) a += gs[lane + 32 * t] * W1[k * Hd + lane + 32 * t];
        #pragma unroll
        for (int o = 16; o; o >>= 1) a += __shfl_xor_sync(0xffffffffu, a, o);
        if (lane == 0) g_h1[b * Hd + k] = fmaxf(a + b1[k], 0.f);
    }
}

// ---------------- BatchNorm stats, parallel (16 blocks) --------------------
__global__ void bn_kernel(const float* __restrict__ gamma, const float* __restrict__ beta) {
    __shared__ float ps[16][16];
    __shared__ float pq[16][16];
    int tid = threadIdx.x;
    int kl = tid & 15, bl = tid >> 4;
    int k = blockIdx.x * 16 + kl;
    float s = 0.f, sq = 0.f;
    #pragma unroll
    for (int j = 0; j < 16; j++) {
        float v = g_h1[(bl + 16 * j) * Hd + k];
        s += v; sq += v * v;
    }
    ps[bl][kl] = s; pq[bl][kl] = sq;
    __syncthreads();
    if (tid < 16) {
        float ts = 0.f, tq = 0.f;
        #pragma unroll
        for (int j = 0; j < 16; j++) { ts += ps[j][tid]; tq += pq[j][tid]; }
        int kk = blockIdx.x * 16 + tid;
        float mu = ts * (1.f / Bd);
        float var = tq * (1.f / Bd) - mu * mu;
        float sc = rsqrtf(var + 1e-5f) * gamma[kk];
        g_scale[kk] = sc; g_shift[kk] = beta[kk] - mu * sc;
    }
}

__global__ void palette_kernel(const float* __restrict__ W2, const float* __restrict__ b2,
                               float* __restrict__ out_pal) {
    int b = blockIdx.x, lane = threadIdx.x & 31, p = threadIdx.x >> 5;
    if (p >= Pd) return;
    float a = 0.f;
    #pragma unroll
    for (int t = 0; t < 8; t++) {
        int h = lane + 32 * t;
        a += (g_h1[b * Hd + h] * g_scale[h] + g_shift[h]) * W2[p * Hd + h];
    }
    #pragma unroll
    for (int o = 16; o; o >>= 1) a += __shfl_xor_sync(0xffffffffu, a, o);
    if (lane == 0) out_pal[b * Pd + p] = a + b2[p];
}

extern "C" void kernel_launch(void* const* d_in, const int* in_sizes, int n_in,
                              void* d_out, int out_size) {
    const float* last_palette = (const float*)d_in[0];
    const float* ldh          = (const float*)d_in[1];
    const float* enc          = (const float*)d_in[2];
    const float* We           = (const float*)d_in[3];
    const float* be           = (const float*)d_in[4];
    const float* Wh           = (const float*)d_in[5];
    const float* bh           = (const float*)d_in[6];
    const float* Wv           = (const float*)d_in[7];
    const float* W_ih         = (const float*)d_in[9];
    const float* b_ih         = (const float*)d_in[10];
    const float* W_hh         = (const float*)d_in[11];
    const float* b_hh         = (const float*)d_in[12];
    const float* W1           = (const float*)d_in[13];
    const float* b1           = (const float*)d_in[14];
    const float* gamma        = (const float*)d_in[15];
    const float* beta         = (const float*)d_in[16];
    const float* W2           = (const float*)d_in[17];
    const float* b2           = (const float*)d_in[18];

    float* out      = (float*)d_out;
    float* out_pal  = out;
    float* out_ctx  = out + Bd * Pd;
    float* out_gru  = out + Bd * Pd + Bd * Hd;
    float* out_attn = out + Bd * Pd + 2 * Bd * Hd;

    static bool attr_done = false;
    if (!attr_done) {
        cudaFuncSetAttribute(energy_hmma_kernel,
                             cudaFuncAttributeMaxDynamicSharedMemorySize, ESMEM);
        attr_done = true;
    }

    hid2_kernel<<<Bd, 256>>>(ldh, Wh, bh, be);
    energy_hmma_kernel<<<NCTAS, 256, ESMEM>>>(enc, We, Wv);
    softmax_kernel<<<Bd, 256>>>(out_attn);
    zero_ctx_kernel<<<Bd, 256>>>(out_ctx);
    ctx_part_kernel<<<dim3(Bd, 8), 256>>>(enc, out_attn, out_ctx);
    gru_gemm_kernel<<<96, 256>>>(last_palette, ldh, out_ctx, W_ih, W_hh);
    gru_h1_kernel<<<Bd, 256>>>(ldh, b_ih, b_hh, W1, b1, out_gru);
    bn_kernel<<<16, 256>>>(gamma, beta);
    palette_kernel<<<Bd, 128>>>(W2, b2, out_pal);
}

// round 14
// speedup vs baseline: 1.1573x; 1.0231x over previous
#include <cuda_runtime.h>
#include <cuda_bf16.h>
#include <cstdint>

#define Sd 2048
#define Bd 256
#define Hd 256
#define Pd 3
#define NCTAS 148
#define ITEMS 16384           // 256 b * 64 s-chunks of 32

__device__ float g_hid2[Bd * Hd];
__device__ float g_attn_part[4 * Bd * Sd];   // per-colgroup energy partials
__device__ float g_h1[Bd * Hd];
__device__ float g_scale[Hd];
__device__ float g_shift[Hd];
__device__ float g_gi[Bd * 3 * Hd];
__device__ float g_gh[Bd * 3 * Hd];

__device__ __forceinline__ float sigmoidf_(float x) {
    return 1.0f / (1.0f + __expf(-x));
}
__device__ __forceinline__ float tanh_ap(float x) {
    float y; asm("tanh.approx.f32 %0, %1;" : "=f"(y) : "f"(x)); return y;
}
__device__ __forceinline__ uint32_t smem_u32f(const void* p) {
    uint32_t a;
    asm("{ .reg .u64 t; cvta.to.shared.u64 t, %1; cvt.u32.u64 %0, t; }" : "=r"(a) : "l"(p));
    return a;
}
__device__ __forceinline__ void ldsm_x4(uint32_t& r0, uint32_t& r1,
                                        uint32_t& r2, uint32_t& r3, uint32_t addr) {
    asm volatile("ldmatrix.sync.aligned.m8n8.x4.shared.b16 {%0,%1,%2,%3}, [%4];"
                 : "=r"(r0), "=r"(r1), "=r"(r2), "=r"(r3) : "r"(addr));
}
__device__ __forceinline__ void mma16816(float* d, uint32_t a0, uint32_t a1,
                                         uint32_t a2, uint32_t a3,
                                         uint32_t b0, uint32_t b1) {
    asm volatile(
        "mma.sync.aligned.m16n8k16.row.col.f32.bf16.bf16.f32 "
        "{%0,%1,%2,%3},{%4,%5,%6,%7},{%8,%9},{%0,%1,%2,%3};"
        : "+f"(d[0]), "+f"(d[1]), "+f"(d[2]), "+f"(d[3])
        : "r"(a0), "r"(a1), "r"(a2), "r"(a3), "r"(b0), "r"(b1));
}
#define CP_ASYNC16(dst, src) \
    asm volatile("cp.async.cg.shared.global [%0], [%1], 16;" :: "r"(dst), "l"(src))
#define CP_COMMIT() asm volatile("cp.async.commit_group;" ::: "memory")
#define CP_WAIT0()  asm volatile("cp.async.wait_group 0;" ::: "memory")

// hid2[b,k] = 0.5*(ldh@Wh^T + bh + be)
__global__ void hid2_kernel(const float* __restrict__ ldh, const float* __restrict__ Wh,
                            const float* __restrict__ bh, const float* __restrict__ be) {
    int b = blockIdx.x, tid = threadIdx.x, lane = tid & 31, warp = tid >> 5;
    __shared__ float hsm[Hd];
    hsm[tid] = ldh[b * Hd + tid];
    __syncthreads();
    for (int k = warp; k < Hd; k += 8) {
        float a = 0.f;
        #pragma unroll
        for (int t = 0; t < 8; t++) a += hsm[lane + 32 * t] * Wh[k * Hd + lane + 32 * t];
        #pragma unroll
        for (int o = 16; o; o >>= 1) a += __shfl_xor_sync(0xffffffffu, a, o);
        if (lane == 0) g_hid2[b * Hd + k] = 0.5f * (a + bh[k] + be[k]);
    }
}

// ---------------- persistent HMMA energy kernel, fused fp32 ingest --------
#define WST 264
#define OFF_WE 0
#define SZ_WE (256 * WST * 2)                // 135168
#define OFF_ST SZ_WE                         // fp32 stage, linear 32KB
#define SZ_ST 32768
#define OFF_X0 (OFF_ST + SZ_ST)              // 167936
#define SZ_X (32 * WST * 2)                  // 16896
#define OFF_X1 (OFF_X0 + SZ_X)               // 184832
#define OFF_WV (OFF_X1 + SZ_X)               // 201728
#define ESMEM (OFF_WV + 1024)                // 202752

__global__ __launch_bounds__(256, 1)
void energy_hmma_kernel(const float* __restrict__ X, const float* __restrict__ We,
                        const float* __restrict__ Wv) {
    extern __shared__ char smem[];
    const uint32_t sm32 = smem_u32f(smem);
    const int tid = threadIdx.x, lane = tid & 31, wid = tid >> 5;
    float* wv2s = (float*)(smem + OFF_WV);

    // stage We (row n = tid) as bf16 [n][k] stride 264, once
    {
        const float2* wr = (const float2*)(We + tid * Hd);
        __nv_bfloat16* wd = (__nv_bfloat16*)(smem + OFF_WE) + tid * WST;
        #pragma unroll 8
        for (int j = 0; j < 128; j++) {
            float2 v = wr[j];
            __nv_bfloat162 p = __floats2bfloat162_rn(v.x, v.y);
            *(uint32_t*)(wd + 2 * j) = *(uint32_t*)&p;
        }
    }
    wv2s[tid] = 0.5f * Wv[tid];

    const int start = (ITEMS * blockIdx.x) / NCTAS;
    const int n = (ITEMS * (blockIdx.x + 1)) / NCTAS - start;

    auto issue = [&](int i) {
        int item = start + i;
        int bb = item >> 6, s0 = (item & 63) << 5;
        #pragma unroll
        for (int k = 0; k < 8; k++) {
            int c = tid + k * 256;                 // float4 index 0..2047
            int row = c >> 6, col16 = c & 63;
            const char* src = (const char*)(X + ((size_t)(s0 + row) * Bd + bb) * Hd)
                            + col16 * 16;
            CP_ASYNC16(sm32 + OFF_ST + (uint32_t)c * 16, src);
        }
    };
    auto convert = [&](int buf) {
        const float4* st = (const float4*)(smem + OFF_ST);
        __nv_bfloat16* xd = (__nv_bfloat16*)(smem + (buf ? OFF_X1 : OFF_X0));
        #pragma unroll
        for (int j = 0; j < 8; j++) {
            int q = tid + 256 * j;
            float4 f = st[q];
            int row = q >> 6, c4 = q & 63;
            __nv_bfloat162 a = __floats2bfloat162_rn(f.x, f.y);
            __nv_bfloat162 b = __floats2bfloat162_rn(f.z, f.w);
            uint2 u = { *(uint32_t*)&a, *(uint32_t*)&b };
            *(uint2*)(xd + row * WST + c4 * 4) = u;
        }
    };

    issue(0); CP_COMMIT();
    CP_WAIT0();
    convert(0);
    if (n > 1) { issue(1); CP_COMMIT(); }
    __syncthreads();

    const int rg = wid & 1, cg = wid >> 1;
    const int r0 = rg * 16, c0 = cg * 64;
    const uint32_t a_rel = (uint32_t)((r0 + (lane & 15)) * WST + (lane >> 4) * 8) * 2;
    const uint32_t b_base = sm32 + OFF_WE
        + (uint32_t)((c0 + (lane & 7) + ((lane >> 4) << 3)) * WST + ((lane >> 3) & 1) * 8) * 2;

    for (int i = 0; i < n; i++) {
        const int item = start + i;
        const int bb = item >> 6, s0 = (item & 63) << 5;

        float d[8][4];
        #pragma unroll
        for (int nt = 0; nt < 8; nt++)
            #pragma unroll
            for (int j = 0; j < 4; j++) d[nt][j] = 0.f;

        const uint32_t abase = sm32 + ((i & 1) ? OFF_X1 : OFF_X0) + a_rel;

        // software-pipelined MMA: prefetch A(ks+1) and B(next np) one step early
        uint32_t a[4], bf[4];
        ldsm_x4(a[0], a[1], a[2], a[3], abase);
        ldsm_x4(bf[0], bf[1], bf[2], bf[3], b_base);
        #pragma unroll
        for (int ks = 0; ks < 16; ks++) {
            uint32_t an[4];
            if (ks < 15) ldsm_x4(an[0], an[1], an[2], an[3], abase + (ks + 1) * 32);
            #pragma unroll
            for (int np = 0; np < 4; np++) {
                uint32_t bn[4];
                if (!(ks == 15 && np == 3)) {
                    uint32_t nxt = (np < 3)
                        ? b_base + (uint32_t)((np + 1) * 16 * WST) * 2 + ks * 32
                        : b_base + (ks + 1) * 32;
                    ldsm_x4(bn[0], bn[1], bn[2], bn[3], nxt);
                }
                mma16816(d[2 * np],     a[0], a[1], a[2], a[3], bf[0], bf[1]);
                mma16816(d[2 * np + 1], a[0], a[1], a[2], a[3], bf[2], bf[3]);
                #pragma unroll
                for (int q = 0; q < 4; q++) bf[q] = bn[q];
            }
            #pragma unroll
            for (int q = 0; q < 4; q++) a[q] = an[q];
        }

        // pipeline: finish item i+1's DRAM load, convert, prefetch i+2
        if (i + 1 < n) {
            CP_WAIT0();
            convert((i + 1) & 1);
            if (i + 2 < n) { issue(i + 2); CP_COMMIT(); }
        }
        __syncthreads();

        // epilogue: tanh + Wv dot -> g_attn_part[cg]
        {
            const float* h2 = g_hid2 + bb * Hd;
            float p0 = 0.f, p1 = 0.f;
            #pragma unroll
            for (int nt = 0; nt < 8; nt++) {
                int col = c0 + nt * 8 + (lane & 3) * 2;
                float w0 = wv2s[col], w1 = wv2s[col + 1];
                float h0 = __ldg(h2 + col), h1 = __ldg(h2 + col + 1);
                p0 += w0 * tanh_ap(fmaf(0.5f, d[nt][0], h0))
                    + w1 * tanh_ap(fmaf(0.5f, d[nt][1], h1));
                p1 += w0 * tanh_ap(fmaf(0.5f, d[nt][2], h0))
                    + w1 * tanh_ap(fmaf(0.5f, d[nt][3], h1));
            }
            p0 += __shfl_xor_sync(0xffffffffu, p0, 1);
            p0 += __shfl_xor_sync(0xffffffffu, p0, 2);
            p1 += __shfl_xor_sync(0xffffffffu, p1, 1);
            p1 += __shfl_xor_sync(0xffffffffu, p1, 2);
            if ((lane & 3) == 0) {
                int q = lane >> 2;
                size_t base = (size_t)cg * (Bd * Sd) + (size_t)bb * Sd + s0 + r0 + q;
                g_attn_part[base] = p0;
                g_attn_part[base + 8] = p1;
            }
        }
    }
}

// ---------------- softmax (sums 4 slices) + zero out_ctx -------------------
__global__ void softmax_kernel(float* __restrict__ attn, float* __restrict__ out_ctx) {
    int b = blockIdx.x, tid = threadIdx.x;
    out_ctx[b * Hd + tid] = 0.f;    // zero ctx accumulator (folded launch)
    const size_t sl = (size_t)Bd * Sd;
    float* row = attn + b * Sd;
    float v[8]; float mx = -1e30f;
    #pragma unroll
    for (int t = 0; t < 8; t++) {
        size_t idx = (size_t)b * Sd + tid + 256 * t;
        v[t] = g_attn_part[idx] + g_attn_part[sl + idx]
             + g_attn_part[2 * sl + idx] + g_attn_part[3 * sl + idx];
        mx = fmaxf(mx, v[t]);
    }
    __shared__ float redm[8]; __shared__ float reds[8];
    #pragma unroll
    for (int o = 16; o; o >>= 1) mx = fmaxf(mx, __shfl_xor_sync(0xffffffffu, mx, o));
    if ((tid & 31) == 0) redm[tid >> 5] = mx;
    __syncthreads();
    mx = redm[0];
    #pragma unroll
    for (int i = 1; i < 8; i++) mx = fmaxf(mx, redm[i]);
    float sum = 0.f;
    #pragma unroll
    for (int t = 0; t < 8; t++) { v[t] = __expf(v[t] - mx); sum += v[t]; }
    #pragma unroll
    for (int o = 16; o; o >>= 1) sum += __shfl_xor_sync(0xffffffffu, sum, o);
    if ((tid & 31) == 0) reds[tid >> 5] = sum;
    __syncthreads();
    sum = 0.f;
    #pragma unroll
    for (int i = 0; i < 8; i++) sum += reds[i];
    float inv = 1.f / sum;
    #pragma unroll
    for (int t = 0; t < 8; t++) row[tid + 256 * t] = v[t] * inv;
}

// ---------------- context partials: streamed fp32 + atomics ---------------
__global__ void ctx_part_kernel(const float* __restrict__ enc,
                                const float* __restrict__ attn,
                                float* __restrict__ out_ctx) {
    int b = blockIdx.x, sc = blockIdx.y, h = threadIdx.x;
    int s0 = sc * 256;
    const float* wrow = attn + b * Sd + s0;
    const float* e = enc + ((size_t)s0 * Bd + b) * Hd + h;
    float a0 = 0.f, a1 = 0.f, a2 = 0.f, a3 = 0.f;
    #pragma unroll 2
    for (int s = 0; s < 256; s += 4) {
        a0 += wrow[s + 0] * __ldcs(e + (size_t)(s + 0) * (Bd * Hd));
        a1 += wrow[s + 1] * __ldcs(e + (size_t)(s + 1) * (Bd * Hd));
        a2 += wrow[s + 2] * __ldcs(e + (size_t)(s + 2) * (Bd * Hd));
        a3 += wrow[s + 3] * __ldcs(e + (size_t)(s + 3) * (Bd * Hd));
    }
    atomicAdd(&out_ctx[b * Hd + h], (a0 + a1) + (a2 + a3));
}

// ---------------- GRU: weight-stationary gate GEMM ------------------------
__global__ __launch_bounds__(256)
void gru_gemm_kernel(const float* __restrict__ last_palette,
                     const float* __restrict__ ldh, const float* __restrict__ ctx,
                     const float* __restrict__ W_ih, const float* __restrict__ W_hh) {
    __shared__ float Wi[8][260];
    __shared__ float Whh[8][256];
    const int tid = threadIdx.x, lane = tid & 31, warp = tid >> 5;
    const int k0 = blockIdx.x * 8;
    const int KX = Hd + Pd;   // 259
    for (int idx = tid; idx < 8 * KX; idx += 256)
        Wi[idx / KX][idx % KX] = W_ih[(size_t)(k0 + idx / KX) * KX + idx % KX];
    for (int idx = tid; idx < 8 * Hd; idx += 256)
        Whh[idx >> 8][idx & 255] = W_hh[(size_t)(k0 + (idx >> 8)) * Hd + (idx & 255)];
    __syncthreads();

    for (int it = 0; it < 32; it++) {
        int b = warp + 8 * it;
        float xr[8], hr[8];
        #pragma unroll
        for (int t = 0; t < 8; t++) {
            int j = lane + 32 * t;
            xr[t] = (j < 3) ? last_palette[b * Pd + j] : ctx[b * Hd + (j - 3)];
            hr[t] = ldh[b * Hd + j];
        }
        float xe = (lane < 3) ? ctx[b * Hd + 253 + lane] : 0.f;
        #pragma unroll
        for (int o = 0; o < 8; o++) {
            float a = (lane < 3) ? xe * Wi[o][256 + lane] : 0.f;
            float c = 0.f;
            #pragma unroll
            for (int t = 0; t < 8; t++) {
                a += xr[t] * Wi[o][lane + 32 * t];
                c += hr[t] * Whh[o][lane + 32 * t];
            }
            #pragma unroll
            for (int off = 16; off; off >>= 1) {
                a += __shfl_xor_sync(0xffffffffu, a, off);
                c += __shfl_xor_sync(0xffffffffu, c, off);
            }
            if (lane == 0) {
                g_gi[(size_t)b * (3 * Hd) + k0 + o] = a;
                g_gh[(size_t)b * (3 * Hd) + k0 + o] = c;
            }
        }
    }
}

// ---------------- GRU combine + h1 (fused, per-b block) -------------------
__global__ void gru_h1_kernel(const float* __restrict__ ldh,
                              const float* __restrict__ b_ih,
                              const float* __restrict__ b_hh,
                              const float* __restrict__ W1,
                              const float* __restrict__ b1,
                              float* __restrict__ out_gru) {
    int b = blockIdx.x, tid = threadIdx.x, lane = tid & 31, warp = tid >> 5;
    __shared__ float gs[Hd];
    {
        int k = tid;
        const float* gi = g_gi + (size_t)b * (3 * Hd);
        const float* gh = g_gh + (size_t)b * (3 * Hd);
        float r = sigmoidf_(gi[k] + b_ih[k] + gh[k] + b_hh[k]);
        float z = sigmoidf_(gi[Hd + k] + b_ih[Hd + k] + gh[Hd + k] + b_hh[Hd + k]);
        float nn = tanhf(gi[2 * Hd + k] + b_ih[2 * Hd + k]
                         + r * (gh[2 * Hd + k] + b_hh[2 * Hd + k]));
        float g = (1.f - z) * nn + z * ldh[b * Hd + k];
        out_gru[b * Hd + k] = g;
        gs[k] = g;
    }
    __syncthreads();
    for (int k = warp; k < Hd; k += 8) {
        float a = 0.f;
        #pragma unroll
        for (int t = 0; t < 8; t++) a += gs[lane + 32 * t] * W1[k * Hd + lane + 32 * t];
        #pragma unroll
        for (int o = 16; o; o >>= 1) a += __shfl_xor_sync(0xffffffffu, a, o);
        if (lane == 0) g_h1[b * Hd + k] = fmaxf(a + b1[k], 0.f);
    }
}

// ---------------- BatchNorm stats, parallel (16 blocks) --------------------
__global__ void bn_kernel(const float* __restrict__ gamma, const float* __restrict__ beta) {
    __shared__ float ps[16][16];
    __shared__ float pq[16][16];
    int tid = threadIdx.x;
    int kl = tid & 15, bl = tid >> 4;
    int k = blockIdx.x * 16 + kl;
    float s = 0.f, sq = 0.f;
    #pragma unroll
    for (int j = 0; j < 16; j++) {
        float v = g_h1[(bl + 16 * j) * Hd + k];
        s += v; sq += v * v;
    }
    ps[bl][kl] = s; pq[bl][kl] = sq;
    __syncthreads();
    if (tid < 16) {
        float ts = 0.f, tq = 0.f;
        #pragma unroll
        for (int j = 0; j < 16; j++) { ts += ps[j][tid]; tq += pq[j][tid]; }
        int kk = blockIdx.x * 16 + tid;
        float mu = ts * (1.f / Bd);
        float var = tq * (1.f / Bd) - mu * mu;
        float sc = rsqrtf(var + 1e-5f) * gamma[kk];
        g_scale[kk] = sc; g_shift[kk] = beta[kk] - mu * sc;
    }
}

__global__ void palette_kernel(const float* __restrict__ W2, const float* __restrict__ b2,
                               float* __restrict__ out_pal) {
    int b = blockIdx.x, lane = threadIdx.x & 31, p = threadIdx.x >> 5;
    if (p >= Pd) return;
    float a = 0.f;
    #pragma unroll
    for (int t = 0; t < 8; t++) {
        int h = lane + 32 * t;
        a += (g_h1[b * Hd + h] * g_scale[h] + g_shift[h]) * W2[p * Hd + h];
    }
    #pragma unroll
    for (int o = 16; o; o >>= 1) a += __shfl_xor_sync(0xffffffffu, a, o);
    if (lane == 0) out_pal[b * Pd + p] = a + b2[p];
}

extern "C" void kernel_launch(void* const* d_in, const int* in_sizes, int n_in,
                              void* d_out, int out_size) {
    const float* last_palette = (const float*)d_in[0];
    const float* ldh          = (const float*)d_in[1];
    const float* enc          = (const float*)d_in[2];
    const float* We           = (const float*)d_in[3];
    const float* be           = (const float*)d_in[4];
    const float* Wh           = (const float*)d_in[5];
    const float* bh           = (const float*)d_in[6];
    const float* Wv           = (const float*)d_in[7];
    const float* W_ih         = (const float*)d_in[9];
    const float* b_ih         = (const float*)d_in[10];
    const float* W_hh         = (const float*)d_in[11];
    const float* b_hh         = (const float*)d_in[12];
    const float* W1           = (const float*)d_in[13];
    const float* b1           = (const float*)d_in[14];
    const float* gamma        = (const float*)d_in[15];
    const float* beta         = (const float*)d_in[16];
    const float* W2           = (const float*)d_in[17];
    const float* b2           = (const float*)d_in[18];

    float* out      = (float*)d_out;
    float* out_pal  = out;
    float* out_ctx  = out + Bd * Pd;
    float* out_gru  = out + Bd * Pd + Bd * Hd;
    float* out_attn = out + Bd * Pd + 2 * Bd * Hd;

    static bool attr_done = false;
    if (!attr_done) {
        cudaFuncSetAttribute(energy_hmma_kernel,
                             cudaFuncAttributeMaxDynamicSharedMemorySize, ESMEM);
        attr_done = true;
    }

    hid2_kernel<<<Bd, 256>>>(ldh, Wh, bh, be);
    energy_hmma_kernel<<<NCTAS, 256, ESMEM>>>(enc, We, Wv);
    softmax_kernel<<<Bd, 256>>>(out_attn, out_ctx);
    ctx_part_kernel<<<dim3(Bd, 8), 256>>>(enc, out_attn, out_ctx);
    gru_gemm_kernel<<<96, 256>>>(last_palette, ldh, out_ctx, W_ih, W_hh);
    gru_h1_kernel<<<Bd, 256>>>(ldh, b_ih, b_hh, W1, b1, out_gru);
    bn_kernel<<<16, 256>>>(gamma, beta);
    palette_kernel<<<Bd, 128>>>(W2, b2, out_pal);
}

// round 15
// speedup vs baseline: 1.2262x; 1.0595x over previous
#include <cuda_runtime.h>
#include <cuda_bf16.h>
#include <cstdint>

#define Sd 2048
#define Bd 256
#define Hd 256
#define Pd 3
#define NCTAS 148
#define ITEMS 16384           // 256 b * 64 s-chunks of 32

__device__ float g_hid2[Bd * Hd];
__device__ float g_attn_part[8 * Bd * Sd];   // per-32col-group energy partials
__device__ float g_h1[Bd * Hd];
__device__ float g_scale[Hd];
__device__ float g_shift[Hd];
__device__ float g_gi[Bd * 3 * Hd];
__device__ float g_gh[Bd * 3 * Hd];

__device__ __forceinline__ float sigmoidf_(float x) {
    return 1.0f / (1.0f + __expf(-x));
}
__device__ __forceinline__ float tanh_ap(float x) {
    float y; asm("tanh.approx.f32 %0, %1;" : "=f"(y) : "f"(x)); return y;
}
__device__ __forceinline__ uint32_t smem_u32f(const void* p) {
    uint32_t a;
    asm("{ .reg .u64 t; cvta.to.shared.u64 t, %1; cvt.u32.u64 %0, t; }" : "=r"(a) : "l"(p));
    return a;
}
__device__ __forceinline__ void ldsm_x4(uint32_t& r0, uint32_t& r1,
                                        uint32_t& r2, uint32_t& r3, uint32_t addr) {
    asm volatile("ldmatrix.sync.aligned.m8n8.x4.shared.b16 {%0,%1,%2,%3}, [%4];"
                 : "=r"(r0), "=r"(r1), "=r"(r2), "=r"(r3) : "r"(addr));
}
__device__ __forceinline__ void mma16816(float* d, uint32_t a0, uint32_t a1,
                                         uint32_t a2, uint32_t a3,
                                         uint32_t b0, uint32_t b1) {
    asm volatile(
        "mma.sync.aligned.m16n8k16.row.col.f32.bf16.bf16.f32 "
        "{%0,%1,%2,%3},{%4,%5,%6,%7},{%8,%9},{%0,%1,%2,%3};"
        : "+f"(d[0]), "+f"(d[1]), "+f"(d[2]), "+f"(d[3])
        : "r"(a0), "r"(a1), "r"(a2), "r"(a3), "r"(b0), "r"(b1));
}
#define CP_ASYNC16(dst, src) \
    asm volatile("cp.async.cg.shared.global [%0], [%1], 16;" :: "r"(dst), "l"(src))
#define CP_COMMIT() asm volatile("cp.async.commit_group;" ::: "memory")
#define CP_WAIT0()  asm volatile("cp.async.wait_group 0;" ::: "memory")

// hid2[b,k] = 0.5*(ldh@Wh^T + bh + be)
__global__ void hid2_kernel(const float* __restrict__ ldh, const float* __restrict__ Wh,
                            const float* __restrict__ bh, const float* __restrict__ be) {
    int b = blockIdx.x, tid = threadIdx.x, lane = tid & 31, warp = tid >> 5;
    __shared__ float hsm[Hd];
    hsm[tid] = ldh[b * Hd + tid];
    __syncthreads();
    for (int k = warp; k < Hd; k += 8) {
        float a = 0.f;
        #pragma unroll
        for (int t = 0; t < 8; t++) a += hsm[lane + 32 * t] * Wh[k * Hd + lane + 32 * t];
        #pragma unroll
        for (int o = 16; o; o >>= 1) a += __shfl_xor_sync(0xffffffffu, a, o);
        if (lane == 0) g_hid2[b * Hd + k] = 0.5f * (a + bh[k] + be[k]);
    }
}

// ---------------- persistent HMMA energy kernel, B-register-stationary -----
// Warp w owns cols w*32..+31 for all 32 rows; B fragments preloaded to regs.
#define WST 264
#define OFF_WE 0
#define SZ_WE (256 * WST * 2)                // 135168
#define OFF_ST SZ_WE                         // fp32 stage, linear 32KB
#define SZ_ST 32768
#define OFF_X0 (OFF_ST + SZ_ST)              // 167936
#define SZ_X (32 * WST * 2)                  // 16896
#define OFF_X1 (OFF_X0 + SZ_X)               // 184832
#define OFF_WV (OFF_X1 + SZ_X)               // 201728
#define ESMEM (OFF_WV + 1024)                // 202752

__global__ __launch_bounds__(256, 1)
void energy_hmma_kernel(const float* __restrict__ X, const float* __restrict__ We,
                        const float* __restrict__ Wv) {
    extern __shared__ char smem[];
    const uint32_t sm32 = smem_u32f(smem);
    const int tid = threadIdx.x, lane = tid & 31, wid = tid >> 5;
    float* wv2s = (float*)(smem + OFF_WV);

    // stage We (row n = tid) as bf16 [n][k] stride 264, once
    {
        const float2* wr = (const float2*)(We + tid * Hd);
        __nv_bfloat16* wd = (__nv_bfloat16*)(smem + OFF_WE) + tid * WST;
        #pragma unroll 8
        for (int j = 0; j < 128; j++) {
            float2 v = wr[j];
            __nv_bfloat162 p = __floats2bfloat162_rn(v.x, v.y);
            *(uint32_t*)(wd + 2 * j) = *(uint32_t*)&p;
        }
    }
    wv2s[tid] = 0.5f * Wv[tid];

    const int start = (ITEMS * blockIdx.x) / NCTAS;
    const int n = (ITEMS * (blockIdx.x + 1)) / NCTAS - start;

    auto issue = [&](int i) {
        int item = start + i;
        int bb = item >> 6, s0 = (item & 63) << 5;
        #pragma unroll
        for (int k = 0; k < 8; k++) {
            int c = tid + k * 256;                 // float4 index 0..2047
            int row = c >> 6, col16 = c & 63;
            const char* src = (const char*)(X + ((size_t)(s0 + row) * Bd + bb) * Hd)
                            + col16 * 16;
            CP_ASYNC16(sm32 + OFF_ST + (uint32_t)c * 16, src);
        }
    };
    auto convert = [&](int buf) {
        const float4* st = (const float4*)(smem + OFF_ST);
        __nv_bfloat16* xd = (__nv_bfloat16*)(smem + (buf ? OFF_X1 : OFF_X0));
        #pragma unroll
        for (int j = 0; j < 8; j++) {
            int q = tid + 256 * j;
            float4 f = st[q];
            int row = q >> 6, c4 = q & 63;
            __nv_bfloat162 a = __floats2bfloat162_rn(f.x, f.y);
            __nv_bfloat162 b = __floats2bfloat162_rn(f.z, f.w);
            uint2 u = { *(uint32_t*)&a, *(uint32_t*)&b };
            *(uint2*)(xd + row * WST + c4 * 4) = u;
        }
    };

    issue(0); CP_COMMIT();
    CP_WAIT0();
    convert(0);
    if (n > 1) { issue(1); CP_COMMIT(); }
    __syncthreads();

    const int cg = wid;                          // cols cg*32..+31, rows 0..31
    const int c0 = cg * 32;
    const uint32_t a_rel = (uint32_t)(((lane & 15)) * WST + (lane >> 4) * 8) * 2;
    const uint32_t b_base = sm32 + OFF_WE
        + (uint32_t)((c0 + (lane & 7) + ((lane >> 4) << 3)) * WST + ((lane >> 3) & 1) * 8) * 2;

    // preload ALL B fragments for this warp's 32 cols x K=256 into registers
    uint32_t breg[16][8];
    #pragma unroll
    for (int ks = 0; ks < 16; ks++) {
        ldsm_x4(breg[ks][0], breg[ks][1], breg[ks][2], breg[ks][3],
                b_base + ks * 32);                              // nt 0,1
        ldsm_x4(breg[ks][4], breg[ks][5], breg[ks][6], breg[ks][7],
                b_base + (uint32_t)(16 * WST) * 2 + ks * 32);   // nt 2,3
    }

    for (int i = 0; i < n; i++) {
        const int item = start + i;
        const int bb = item >> 6, s0 = (item & 63) << 5;

        float d[2][4][4];
        #pragma unroll
        for (int mt = 0; mt < 2; mt++)
            #pragma unroll
            for (int nt = 0; nt < 4; nt++)
                #pragma unroll
                for (int j = 0; j < 4; j++) d[mt][nt][j] = 0.f;

        const uint32_t abase = sm32 + ((i & 1) ? OFF_X1 : OFF_X0) + a_rel;

        // A software-pipelined; B from registers only
        uint32_t a0[4], a1[4];
        ldsm_x4(a0[0], a0[1], a0[2], a0[3], abase);
        ldsm_x4(a1[0], a1[1], a1[2], a1[3], abase + (uint32_t)(16 * WST) * 2);
        #pragma unroll
        for (int ks = 0; ks < 16; ks++) {
            uint32_t an0[4], an1[4];
            if (ks < 15) {
                ldsm_x4(an0[0], an0[1], an0[2], an0[3], abase + (ks + 1) * 32);
                ldsm_x4(an1[0], an1[1], an1[2], an1[3],
                        abase + (uint32_t)(16 * WST) * 2 + (ks + 1) * 32);
            }
            #pragma unroll
            for (int nt = 0; nt < 4; nt++) {
                mma16816(d[0][nt], a0[0], a0[1], a0[2], a0[3],
                         breg[ks][2 * nt], breg[ks][2 * nt + 1]);
                mma16816(d[1][nt], a1[0], a1[1], a1[2], a1[3],
                         breg[ks][2 * nt], breg[ks][2 * nt + 1]);
            }
            #pragma unroll
            for (int q = 0; q < 4; q++) { a0[q] = an0[q]; a1[q] = an1[q]; }
        }

        // pipeline: finish item i+1's DRAM load, convert, prefetch i+2
        if (i + 1 < n) {
            CP_WAIT0();
            convert((i + 1) & 1);
            if (i + 2 < n) { issue(i + 2); CP_COMMIT(); }
        }
        __syncthreads();

        // epilogue: tanh + Wv dot over this warp's 32 cols -> slice cg
        {
            const float* h2 = g_hid2 + bb * Hd;
            float p[4] = {0.f, 0.f, 0.f, 0.f};
            #pragma unroll
            for (int nt = 0; nt < 4; nt++) {
                int col = c0 + nt * 8 + (lane & 3) * 2;
                float w0 = wv2s[col], w1 = wv2s[col + 1];
                float h0 = __ldg(h2 + col), h1 = __ldg(h2 + col + 1);
                #pragma unroll
                for (int mt = 0; mt < 2; mt++) {
                    p[mt * 2 + 0] += w0 * tanh_ap(fmaf(0.5f, d[mt][nt][0], h0))
                                   + w1 * tanh_ap(fmaf(0.5f, d[mt][nt][1], h1));
                    p[mt * 2 + 1] += w0 * tanh_ap(fmaf(0.5f, d[mt][nt][2], h0))
                                   + w1 * tanh_ap(fmaf(0.5f, d[mt][nt][3], h1));
                }
            }
            #pragma unroll
            for (int j = 0; j < 4; j++) {
                p[j] += __shfl_xor_sync(0xffffffffu, p[j], 1);
                p[j] += __shfl_xor_sync(0xffffffffu, p[j], 2);
            }
            if ((lane & 3) == 0) {
                int q = lane >> 2;
                size_t base = (size_t)cg * (Bd * Sd) + (size_t)bb * Sd + s0 + q;
                g_attn_part[base]      = p[0];
                g_attn_part[base + 8]  = p[1];
                g_attn_part[base + 16] = p[2];
                g_attn_part[base + 24] = p[3];
            }
        }
    }
}

// ---------------- softmax (sums 8 slices) + zero out_ctx -------------------
__global__ void softmax_kernel(float* __restrict__ attn, float* __restrict__ out_ctx) {
    int b = blockIdx.x, tid = threadIdx.x;
    out_ctx[b * Hd + tid] = 0.f;
    const size_t sl = (size_t)Bd * Sd;
    float* row = attn + b * Sd;
    float v[8]; float mx = -1e30f;
    #pragma unroll
    for (int t = 0; t < 8; t++) {
        size_t idx = (size_t)b * Sd + tid + 256 * t;
        float a = 0.f;
        #pragma unroll
        for (int s8 = 0; s8 < 8; s8++) a += g_attn_part[s8 * sl + idx];
        v[t] = a;
        mx = fmaxf(mx, a);
    }
    __shared__ float redm[8]; __shared__ float reds[8];
    #pragma unroll
    for (int o = 16; o; o >>= 1) mx = fmaxf(mx, __shfl_xor_sync(0xffffffffu, mx, o));
    if ((tid & 31) == 0) redm[tid >> 5] = mx;
    __syncthreads();
    mx = redm[0];
    #pragma unroll
    for (int i = 1; i < 8; i++) mx = fmaxf(mx, redm[i]);
    float sum = 0.f;
    #pragma unroll
    for (int t = 0; t < 8; t++) { v[t] = __expf(v[t] - mx); sum += v[t]; }
    #pragma unroll
    for (int o = 16; o; o >>= 1) sum += __shfl_xor_sync(0xffffffffu, sum, o);
    if ((tid & 31) == 0) reds[tid >> 5] = sum;
    __syncthreads();
    sum = 0.f;
    #pragma unroll
    for (int i = 0; i < 8; i++) sum += reds[i];
    float inv = 1.f / sum;
    #pragma unroll
    for (int t = 0; t < 8; t++) row[tid + 256 * t] = v[t] * inv;
}

// ---------------- context partials: streamed fp32 + atomics ---------------
__global__ void ctx_part_kernel(const float* __restrict__ enc,
                                const float* __restrict__ attn,
                                float* __restrict__ out_ctx) {
    int b = blockIdx.x, sc = blockIdx.y, h = threadIdx.x;
    int s0 = sc * 256;
    const float* wrow = attn + b * Sd + s0;
    const float* e = enc + ((size_t)s0 * Bd + b) * Hd + h;
    float a0 = 0.f, a1 = 0.f, a2 = 0.f, a3 = 0.f;
    #pragma unroll 4
    for (int s = 0; s < 256; s += 4) {
        a0 += wrow[s + 0] * __ldcs(e + (size_t)(s + 0) * (Bd * Hd));
        a1 += wrow[s + 1] * __ldcs(e + (size_t)(s + 1) * (Bd * Hd));
        a2 += wrow[s + 2] * __ldcs(e + (size_t)(s + 2) * (Bd * Hd));
        a3 += wrow[s + 3] * __ldcs(e + (size_t)(s + 3) * (Bd * Hd));
    }
    atomicAdd(&out_ctx[b * Hd + h], (a0 + a1) + (a2 + a3));
}

// ---------------- GRU: weight-stationary gate GEMM ------------------------
__global__ __launch_bounds__(256)
void gru_gemm_kernel(const float* __restrict__ last_palette,
                     const float* __restrict__ ldh, const float* __restrict__ ctx,
                     const float* __restrict__ W_ih, const float* __restrict__ W_hh) {
    __shared__ float Wi[8][260];
    __shared__ float Whh[8][256];
    const int tid = threadIdx.x, lane = tid & 31, warp = tid >> 5;
    const int k0 = blockIdx.x * 8;
    const int KX = Hd + Pd;   // 259
    for (int idx = tid; idx < 8 * KX; idx += 256)
        Wi[idx / KX][idx % KX] = W_ih[(size_t)(k0 + idx / KX) * KX + idx % KX];
    for (int idx = tid; idx < 8 * Hd; idx += 256)
        Whh[idx >> 8][idx & 255] = W_hh[(size_t)(k0 + (idx >> 8)) * Hd + (idx & 255)];
    __syncthreads();

    for (int it = 0; it < 32; it++) {
        int b = warp + 8 * it;
        float xr[8], hr[8];
        #pragma unroll
        for (int t = 0; t < 8; t++) {
            int j = lane + 32 * t;
            xr[t] = (j < 3) ? last_palette[b * Pd + j] : ctx[b * Hd + (j - 3)];
            hr[t] = ldh[b * Hd + j];
        }
        float xe = (lane < 3) ? ctx[b * Hd + 253 + lane] : 0.f;
        #pragma unroll
        for (int o = 0; o < 8; o++) {
            float a = (lane < 3) ? xe * Wi[o][256 + lane] : 0.f;
            float c = 0.f;
            #pragma unroll
            for (int t = 0; t < 8; t++) {
                a += xr[t] * Wi[o][lane + 32 * t];
                c += hr[t] * Whh[o][lane + 32 * t];
            }
            #pragma unroll
            for (int off = 16; off; off >>= 1) {
                a += __shfl_xor_sync(0xffffffffu, a, off);
                c += __shfl_xor_sync(0xffffffffu, c, off);
            }
            if (lane == 0) {
                g_gi[(size_t)b * (3 * Hd) + k0 + o] = a;
                g_gh[(size_t)b * (3 * Hd) + k0 + o] = c;
            }
        }
    }
}

// ---------------- GRU combine + h1 (fused, per-b block) -------------------
__global__ void gru_h1_kernel(const float* __restrict__ ldh,
                              const float* __restrict__ b_ih,
                              const float* __restrict__ b_hh,
                              const float* __restrict__ W1,
                              const float* __restrict__ b1,
                              float* __restrict__ out_gru) {
    int b = blockIdx.x, tid = threadIdx.x, lane = tid & 31, warp = tid >> 5;
    __shared__ float gs[Hd];
    {
        int k = tid;
        const float* gi = g_gi + (size_t)b * (3 * Hd);
        const float* gh = g_gh + (size_t)b * (3 * Hd);
        float r = sigmoidf_(gi[k] + b_ih[k] + gh[k] + b_hh[k]);
        float z = sigmoidf_(gi[Hd + k] + b_ih[Hd + k] + gh[Hd + k] + b_hh[Hd + k]);
        float nn = tanhf(gi[2 * Hd + k] + b_ih[2 * Hd + k]
                         + r * (gh[2 * Hd + k] + b_hh[2 * Hd + k]));
        float g = (1.f - z) * nn + z * ldh[b * Hd + k];
        out_gru[b * Hd + k] = g;
        gs[k] = g;
    }
    __syncthreads();
    for (int k = warp; k < Hd; k += 8) {
        float a = 0.f;
        #pragma unroll
        for (int t = 0; t < 8; t++) a += gs[lane + 32 * t] * W1[k * Hd + lane + 32 * t];
        #pragma unroll
        for (int o = 16; o; o >>= 1) a += __shfl_xor_sync(0xffffffffu, a, o);
        if (lane == 0) g_h1[b * Hd + k] = fmaxf(a + b1[k], 0.f);
    }
}

// ---------------- BatchNorm stats, parallel (16 blocks) --------------------
__global__ void bn_kernel(const float* __restrict__ gamma, const float* __restrict__ beta) {
    __shared__ float ps[16][16];
    __shared__ float pq[16][16];
    int tid = threadIdx.x;
    int kl = tid & 15, bl = tid >> 4;
    int k = blockIdx.x * 16 + kl;
    float s = 0.f, sq = 0.f;
    #pragma unroll
    for (int j = 0; j < 16; j++) {
        float v = g_h1[(bl + 16 * j) * Hd + k];
        s += v; sq += v * v;
    }
    ps[bl][kl] = s; pq[bl][kl] = sq;
    __syncthreads();
    if (tid < 16) {
        float ts = 0.f, tq = 0.f;
        #pragma unroll
        for (int j = 0; j < 16; j++) { ts += ps[j][tid]; tq += pq[j][tid]; }
        int kk = blockIdx.x * 16 + tid;
        float mu = ts * (1.f / Bd);
        float var = tq * (1.f / Bd) - mu * mu;
        float sc = rsqrtf(var + 1e-5f) * gamma[kk];
        g_scale[kk] = sc; g_shift[kk] = beta[kk] - mu * sc;
    }
}

__global__ void palette_kernel(const float* __restrict__ W2, const float* __restrict__ b2,
                               float* __restrict__ out_pal) {
    int b = blockIdx.x, lane = threadIdx.x & 31, p = threadIdx.x >> 5;
    if (p >= Pd) return;
    float a = 0.f;
    #pragma unroll
    for (int t = 0; t < 8; t++) {
        int h = lane + 32 * t;
        a += (g_h1[b * Hd + h] * g_scale[h] + g_shift[h]) * W2[p * Hd + h];
    }
    #pragma unroll
    for (int o = 16; o; o >>= 1) a += __shfl_xor_sync(0xffffffffu, a, o);
    if (lane == 0) out_pal[b * Pd + p] = a + b2[p];
}

extern "C" void kernel_launch(void* const* d_in, const int* in_sizes, int n_in,
                              void* d_out, int out_size) {
    const float* last_palette = (const float*)d_in[0];
    const float* ldh          = (const float*)d_in[1];
    const float* enc          = (const float*)d_in[2];
    const float* We           = (const float*)d_in[3];
    const float* be           = (const float*)d_in[4];
    const float* Wh           = (const float*)d_in[5];
    const float* bh           = (const float*)d_in[6];
    const float* Wv           = (const float*)d_in[7];
    const float* W_ih         = (const float*)d_in[9];
    const float* b_ih         = (const float*)d_in[10];
    const float* W_hh         = (const float*)d_in[11];
    const float* b_hh         = (const float*)d_in[12];
    const float* W1           = (const float*)d_in[13];
    const float* b1           = (const float*)d_in[14];
    const float* gamma        = (const float*)d_in[15];
    const float* beta         = (const float*)d_in[16];
    const float* W2           = (const float*)d_in[17];
    const float* b2           = (const float*)d_in[18];

    float* out      = (float*)d_out;
    float* out_pal  = out;
    float* out_ctx  = out + Bd * Pd;
    float* out_gru  = out + Bd * Pd + Bd * Hd;
    float* out_attn = out + Bd * Pd + 2 * Bd * Hd;

    static bool attr_done = false;
    if (!attr_done) {
        cudaFuncSetAttribute(energy_hmma_kernel,
                             cudaFuncAttributeMaxDynamicSharedMemorySize, ESMEM);
        attr_done = true;
    }

    hid2_kernel<<<Bd, 256>>>(ldh, Wh, bh, be);
    energy_hmma_kernel<<<NCTAS, 256, ESMEM>>>(enc, We, Wv);
    softmax_kernel<<<Bd, 256>>>(out_attn, out_ctx);
    ctx_part_kernel<<<dim3(Bd, 8), 256>>>(enc, out_attn, out_ctx);
    gru_gemm_kernel<<<96, 256>>>(last_palette, ldh, out_ctx, W_ih, W_hh);
    gru_h1_kernel<<<Bd, 256>>>(ldh, b_ih, b_hh, W1, b1, out_gru);
    bn_kernel<<<16, 256>>>(gamma, beta);
    palette_kernel<<<Bd, 128>>>(W2, b2, out_pal);
}

// round 16
// speedup vs baseline: 1.2694x; 1.0352x over previous
#include <cuda_runtime.h>
#include <cuda_bf16.h>
#include <cstdint>

#define Sd 2048
#define Bd 256
#define Hd 256
#define Pd 3
#define NCTAS 148
#define ITEMS 16384           // 256 b * 64 s-chunks of 32

__device__ float g_hid2[Bd * Hd];
__device__ float g_attn_part[8 * Bd * Sd];   // per-32col-group energy partials
__device__ float g_h1[Bd * Hd];
__device__ float g_scale[Hd];
__device__ float g_shift[Hd];
__device__ float g_gi[Bd * 3 * Hd];
__device__ float g_gh[Bd * 3 * Hd];

__device__ __forceinline__ float sigmoidf_(float x) {
    return 1.0f / (1.0f + __expf(-x));
}
__device__ __forceinline__ float tanh_ap(float x) {
    float y; asm("tanh.approx.f32 %0, %1;" : "=f"(y) : "f"(x)); return y;
}
__device__ __forceinline__ uint32_t smem_u32f(const void* p) {
    uint32_t a;
    asm("{ .reg .u64 t; cvta.to.shared.u64 t, %1; cvt.u32.u64 %0, t; }" : "=r"(a) : "l"(p));
    return a;
}
__device__ __forceinline__ void ldsm_x4(uint32_t& r0, uint32_t& r1,
                                        uint32_t& r2, uint32_t& r3, uint32_t addr) {
    asm volatile("ldmatrix.sync.aligned.m8n8.x4.shared.b16 {%0,%1,%2,%3}, [%4];"
                 : "=r"(r0), "=r"(r1), "=r"(r2), "=r"(r3) : "r"(addr));
}
__device__ __forceinline__ void mma16816(float* d, uint32_t a0, uint32_t a1,
                                         uint32_t a2, uint32_t a3,
                                         uint32_t b0, uint32_t b1) {
    asm volatile(
        "mma.sync.aligned.m16n8k16.row.col.f32.bf16.bf16.f32 "
        "{%0,%1,%2,%3},{%4,%5,%6,%7},{%8,%9},{%0,%1,%2,%3};"
        : "+f"(d[0]), "+f"(d[1]), "+f"(d[2]), "+f"(d[3])
        : "r"(a0), "r"(a1), "r"(a2), "r"(a3), "r"(b0), "r"(b1));
}
#define CP_ASYNC16(dst, src) \
    asm volatile("cp.async.cg.shared.global [%0], [%1], 16;" :: "r"(dst), "l"(src))
#define CP_COMMIT() asm volatile("cp.async.commit_group;" ::: "memory")
#define CP_WAIT0()  asm volatile("cp.async.wait_group 0;" ::: "memory")

// hid2[b,k] = 0.5*(ldh@Wh^T + bh + be)
__global__ void hid2_kernel(const float* __restrict__ ldh, const float* __restrict__ Wh,
                            const float* __restrict__ bh, const float* __restrict__ be) {
    int b = blockIdx.x, tid = threadIdx.x, lane = tid & 31, warp = tid >> 5;
    __shared__ float hsm[Hd];
    hsm[tid] = ldh[b * Hd + tid];
    __syncthreads();
    for (int k = warp; k < Hd; k += 8) {
        float a = 0.f;
        #pragma unroll
        for (int t = 0; t < 8; t++) a += hsm[lane + 32 * t] * Wh[k * Hd + lane + 32 * t];
        #pragma unroll
        for (int o = 16; o; o >>= 1) a += __shfl_xor_sync(0xffffffffu, a, o);
        if (lane == 0) g_hid2[b * Hd + k] = 0.5f * (a + bh[k] + be[k]);
    }
}

// ---------------- persistent HMMA energy kernel ----------------------------
// B register-stationary; item(i-1) epilogue interleaved into item(i) MMA.
#define WST 264
#define OFF_WE 0
#define SZ_WE (256 * WST * 2)                // 135168
#define OFF_ST SZ_WE                         // fp32 stage, linear 32KB
#define SZ_ST 32768
#define OFF_X0 (OFF_ST + SZ_ST)              // 167936
#define SZ_X (32 * WST * 2)                  // 16896
#define OFF_X1 (OFF_X0 + SZ_X)               // 184832
#define OFF_WV (OFF_X1 + SZ_X)               // 201728
#define ESMEM (OFF_WV + 1024)                // 202752

// one epilogue chunk: 8 tanh for col-group nt of the PREVIOUS item
__device__ __forceinline__ void epi_chunk(const float (&dd)[2][4][4], int nt,
                                          const float* __restrict__ h2p,
                                          const float* __restrict__ wv2s,
                                          float* p, int lane, int c0) {
    int col = c0 + nt * 8 + (lane & 3) * 2;
    float w0 = wv2s[col], w1 = wv2s[col + 1];
    float h0 = __ldg(h2p + col), h1 = __ldg(h2p + col + 1);
    #pragma unroll
    for (int mt = 0; mt < 2; mt++) {
        p[mt * 2 + 0] += w0 * tanh_ap(fmaf(0.5f, dd[mt][nt][0], h0))
                       + w1 * tanh_ap(fmaf(0.5f, dd[mt][nt][1], h1));
        p[mt * 2 + 1] += w0 * tanh_ap(fmaf(0.5f, dd[mt][nt][2], h0))
                       + w1 * tanh_ap(fmaf(0.5f, dd[mt][nt][3], h1));
    }
}

// MMA for cur item with prev item's epilogue interleaved; then reduce+store prev
__device__ __forceinline__ void mma_epi(float (&cur)[2][4][4],
                                        const float (&prev)[2][4][4],
                                        const uint32_t (&breg)[16][8],
                                        uint32_t abase,
                                        const float* __restrict__ h2p,
                                        const float* __restrict__ wv2s,
                                        int lane, int c0,
                                        bool doStore, size_t sbase) {
    #pragma unroll
    for (int mt = 0; mt < 2; mt++)
        #pragma unroll
        for (int nt = 0; nt < 4; nt++)
            #pragma unroll
            for (int j = 0; j < 4; j++) cur[mt][nt][j] = 0.f;

    float p[4] = {0.f, 0.f, 0.f, 0.f};
    #pragma unroll
    for (int ks = 0; ks < 16; ks++) {
        uint32_t a0[4], a1[4];
        ldsm_x4(a0[0], a0[1], a0[2], a0[3], abase + ks * 32);
        ldsm_x4(a1[0], a1[1], a1[2], a1[3],
                abase + (uint32_t)(16 * WST) * 2 + ks * 32);
        if ((ks & 3) == 0) epi_chunk(prev, ks >> 2, h2p, wv2s, p, lane, c0);
        #pragma unroll
        for (int nt = 0; nt < 4; nt++) {
            mma16816(cur[0][nt], a0[0], a0[1], a0[2], a0[3],
                     breg[ks][2 * nt], breg[ks][2 * nt + 1]);
            mma16816(cur[1][nt], a1[0], a1[1], a1[2], a1[3],
                     breg[ks][2 * nt], breg[ks][2 * nt + 1]);
        }
    }
    #pragma unroll
    for (int j = 0; j < 4; j++) {
        p[j] += __shfl_xor_sync(0xffffffffu, p[j], 1);
        p[j] += __shfl_xor_sync(0xffffffffu, p[j], 2);
    }
    if (doStore && (lane & 3) == 0) {
        size_t base = sbase + (lane >> 2);
        g_attn_part[base]      = p[0];
        g_attn_part[base + 8]  = p[1];
        g_attn_part[base + 16] = p[2];
        g_attn_part[base + 24] = p[3];
    }
}

__global__ __launch_bounds__(256, 1)
void energy_hmma_kernel(const float* __restrict__ X, const float* __restrict__ We,
                        const float* __restrict__ Wv) {
    extern __shared__ char smem[];
    const uint32_t sm32 = smem_u32f(smem);
    const int tid = threadIdx.x, lane = tid & 31, wid = tid >> 5;
    float* wv2s = (float*)(smem + OFF_WV);

    // stage We (row n = tid) as bf16 [n][k] stride 264, once
    {
        const float2* wr = (const float2*)(We + tid * Hd);
        __nv_bfloat16* wd = (__nv_bfloat16*)(smem + OFF_WE) + tid * WST;
        #pragma unroll 8
        for (int j = 0; j < 128; j++) {
            float2 v = wr[j];
            __nv_bfloat162 p = __floats2bfloat162_rn(v.x, v.y);
            *(uint32_t*)(wd + 2 * j) = *(uint32_t*)&p;
        }
    }
    wv2s[tid] = 0.5f * Wv[tid];

    const int start = (ITEMS * blockIdx.x) / NCTAS;
    const int n = (ITEMS * (blockIdx.x + 1)) / NCTAS - start;

    auto issue = [&](int i) {
        int item = start + i;
        int bb = item >> 6, s0 = (item & 63) << 5;
        #pragma unroll
        for (int k = 0; k < 8; k++) {
            int c = tid + k * 256;
            int row = c >> 6, col16 = c & 63;
            const char* src = (const char*)(X + ((size_t)(s0 + row) * Bd + bb) * Hd)
                            + col16 * 16;
            CP_ASYNC16(sm32 + OFF_ST + (uint32_t)c * 16, src);
        }
    };
    auto convert = [&](int buf) {
        const float4* st = (const float4*)(smem + OFF_ST);
        __nv_bfloat16* xd = (__nv_bfloat16*)(smem + (buf ? OFF_X1 : OFF_X0));
        #pragma unroll
        for (int j = 0; j < 8; j++) {
            int q = tid + 256 * j;
            float4 f = st[q];
            int row = q >> 6, c4 = q & 63;
            __nv_bfloat162 a = __floats2bfloat162_rn(f.x, f.y);
            __nv_bfloat162 b = __floats2bfloat162_rn(f.z, f.w);
            uint2 u = { *(uint32_t*)&a, *(uint32_t*)&b };
            *(uint2*)(xd + row * WST + c4 * 4) = u;
        }
    };

    issue(0); CP_COMMIT();
    CP_WAIT0();
    convert(0);
    if (n > 1) { issue(1); CP_COMMIT(); }
    __syncthreads();

    const int cg = wid;
    const int c0 = cg * 32;
    const uint32_t a_rel = (uint32_t)(((lane & 15)) * WST + (lane >> 4) * 8) * 2;
    const uint32_t b_base = sm32 + OFF_WE
        + (uint32_t)((c0 + (lane & 7) + ((lane >> 4) << 3)) * WST + ((lane >> 3) & 1) * 8) * 2;

    // preload ALL B fragments (32 cols x K=256) into registers
    uint32_t breg[16][8];
    #pragma unroll
    for (int ks = 0; ks < 16; ks++) {
        ldsm_x4(breg[ks][0], breg[ks][1], breg[ks][2], breg[ks][3],
                b_base + ks * 32);
        ldsm_x4(breg[ks][4], breg[ks][5], breg[ks][6], breg[ks][7],
                b_base + (uint32_t)(16 * WST) * 2 + ks * 32);
    }

    float dA[2][4][4], dB[2][4][4];
    #pragma unroll
    for (int mt = 0; mt < 2; mt++)
        #pragma unroll
        for (int nt = 0; nt < 4; nt++)
            #pragma unroll
            for (int j = 0; j < 4; j++) dB[mt][nt][j] = 0.f;

    int pbb = 0, ps0 = 0;
    for (int i = 0; i < n; i++) {
        const int item = start + i;
        const int bb = item >> 6, s0 = (item & 63) << 5;
        const uint32_t abase = sm32 + ((i & 1) ? OFF_X1 : OFF_X0) + a_rel;
        const float* h2p = g_hid2 + pbb * Hd;
        size_t sbase = (size_t)cg * (Bd * Sd) + (size_t)pbb * Sd + ps0;

        if ((i & 1) == 0)
            mma_epi(dA, dB, breg, abase, h2p, wv2s, lane, c0, i > 0, sbase);
        else
            mma_epi(dB, dA, breg, abase, h2p, wv2s, lane, c0, true, sbase);

        if (i + 1 < n) {
            CP_WAIT0();
            convert((i + 1) & 1);
            if (i + 2 < n) { issue(i + 2); CP_COMMIT(); }
        }
        __syncthreads();
        pbb = bb; ps0 = s0;
    }

    // trailing epilogue for the last item
    {
        const float* h2p = g_hid2 + pbb * Hd;
        float p[4] = {0.f, 0.f, 0.f, 0.f};
        if ((n & 1) == 1) {   // last item parity even -> dA
            #pragma unroll
            for (int nt = 0; nt < 4; nt++) epi_chunk(dA, nt, h2p, wv2s, p, lane, c0);
        } else {
            #pragma unroll
            for (int nt = 0; nt < 4; nt++) epi_chunk(dB, nt, h2p, wv2s, p, lane, c0);
        }
        #pragma unroll
        for (int j = 0; j < 4; j++) {
            p[j] += __shfl_xor_sync(0xffffffffu, p[j], 1);
            p[j] += __shfl_xor_sync(0xffffffffu, p[j], 2);
        }
        if ((lane & 3) == 0) {
            size_t base = (size_t)cg * (Bd * Sd) + (size_t)pbb * Sd + ps0 + (lane >> 2);
            g_attn_part[base]      = p[0];
            g_attn_part[base + 8]  = p[1];
            g_attn_part[base + 16] = p[2];
            g_attn_part[base + 24] = p[3];
        }
    }
}

// ---------------- softmax (sums 8 slices) + zero out_ctx -------------------
__global__ void softmax_kernel(float* __restrict__ attn, float* __restrict__ out_ctx) {
    int b = blockIdx.x, tid = threadIdx.x;
    out_ctx[b * Hd + tid] = 0.f;
    const size_t sl = (size_t)Bd * Sd;
    float* row = attn + b * Sd;
    float v[8]; float mx = -1e30f;
    #pragma unroll
    for (int t = 0; t < 8; t++) {
        size_t idx = (size_t)b * Sd + tid + 256 * t;
        float a = 0.f;
        #pragma unroll
        for (int s8 = 0; s8 < 8; s8++) a += g_attn_part[s8 * sl + idx];
        v[t] = a;
        mx = fmaxf(mx, a);
    }
    __shared__ float redm[8]; __shared__ float reds[8];
    #pragma unroll
    for (int o = 16; o; o >>= 1) mx = fmaxf(mx, __shfl_xor_sync(0xffffffffu, mx, o));
    if ((tid & 31) == 0) redm[tid >> 5] = mx;
    __syncthreads();
    mx = redm[0];
    #pragma unroll
    for (int i = 1; i < 8; i++) mx = fmaxf(mx, redm[i]);
    float sum = 0.f;
    #pragma unroll
    for (int t = 0; t < 8; t++) { v[t] = __expf(v[t] - mx); sum += v[t]; }
    #pragma unroll
    for (int o = 16; o; o >>= 1) sum += __shfl_xor_sync(0xffffffffu, sum, o);
    if ((tid & 31) == 0) reds[tid >> 5] = sum;
    __syncthreads();
    sum = 0.f;
    #pragma unroll
    for (int i = 0; i < 8; i++) sum += reds[i];
    float inv = 1.f / sum;
    #pragma unroll
    for (int t = 0; t < 8; t++) row[tid + 256 * t] = v[t] * inv;
}

// ---------------- context partials: 16 s-chunks, streamed + atomics -------
__global__ void ctx_part_kernel(const float* __restrict__ enc,
                                const float* __restrict__ attn,
                                float* __restrict__ out_ctx) {
    int b = blockIdx.x, sc = blockIdx.y, h = threadIdx.x;
    int s0 = sc * 128;
    const float* wrow = attn + b * Sd + s0;
    const float* e = enc + ((size_t)s0 * Bd + b) * Hd + h;
    float a0 = 0.f, a1 = 0.f, a2 = 0.f, a3 = 0.f;
    #pragma unroll 4
    for (int s = 0; s < 128; s += 4) {
        a0 += wrow[s + 0] * __ldcs(e + (size_t)(s + 0) * (Bd * Hd));
        a1 += wrow[s + 1] * __ldcs(e + (size_t)(s + 1) * (Bd * Hd));
        a2 += wrow[s + 2] * __ldcs(e + (size_t)(s + 2) * (Bd * Hd));
        a3 += wrow[s + 3] * __ldcs(e + (size_t)(s + 3) * (Bd * Hd));
    }
    atomicAdd(&out_ctx[b * Hd + h], (a0 + a1) + (a2 + a3));
}

// ---------------- GRU: weight-stationary gate GEMM ------------------------
__global__ __launch_bounds__(256)
void gru_gemm_kernel(const float* __restrict__ last_palette,
                     const float* __restrict__ ldh, const float* __restrict__ ctx,
                     const float* __restrict__ W_ih, const float* __restrict__ W_hh) {
    __shared__ float Wi[8][260];
    __shared__ float Whh[8][256];
    const int tid = threadIdx.x, lane = tid & 31, warp = tid >> 5;
    const int k0 = blockIdx.x * 8;
    const int KX = Hd + Pd;   // 259
    for (int idx = tid; idx < 8 * KX; idx += 256)
        Wi[idx / KX][idx % KX] = W_ih[(size_t)(k0 + idx / KX) * KX + idx % KX];
    for (int idx = tid; idx < 8 * Hd; idx += 256)
        Whh[idx >> 8][idx & 255] = W_hh[(size_t)(k0 + (idx >> 8)) * Hd + (idx & 255)];
    __syncthreads();

    for (int it = 0; it < 32; it++) {
        int b = warp + 8 * it;
        float xr[8], hr[8];
        #pragma unroll
        for (int t = 0; t < 8; t++) {
            int j = lane + 32 * t;
            xr[t] = (j < 3) ? last_palette[b * Pd + j] : ctx[b * Hd + (j - 3)];
            hr[t] = ldh[b * Hd + j];
        }
        float xe = (lane < 3) ? ctx[b * Hd + 253 + lane] : 0.f;
        #pragma unroll
        for (int o = 0; o < 8; o++) {
            float a = (lane < 3) ? xe * Wi[o][256 + lane] : 0.f;
            float c = 0.f;
            #pragma unroll
            for (int t = 0; t < 8; t++) {
                a += xr[t] * Wi[o][lane + 32 * t];
                c += hr[t] * Whh[o][lane + 32 * t];
            }
            #pragma unroll
            for (int off = 16; off; off >>= 1) {
                a += __shfl_xor_sync(0xffffffffu, a, off);
                c += __shfl_xor_sync(0xffffffffu, c, off);
            }
            if (lane == 0) {
                g_gi[(size_t)b * (3 * Hd) + k0 + o] = a;
                g_gh[(size_t)b * (3 * Hd) + k0 + o] = c;
            }
        }
    }
}

// ---------------- GRU combine + h1 (fused, per-b block) -------------------
__global__ void gru_h1_kernel(const float* __restrict__ ldh,
                              const float* __restrict__ b_ih,
                              const float* __restrict__ b_hh,
                              const float* __restrict__ W1,
                              const float* __restrict__ b1,
                              float* __restrict__ out_gru) {
    int b = blockIdx.x, tid = threadIdx.x, lane = tid & 31, warp = tid >> 5;
    __shared__ float gs[Hd];
    {
        int k = tid;
        const float* gi = g_gi + (size_t)b * (3 * Hd);
        const float* gh = g_gh + (size_t)b * (3 * Hd);
        float r = sigmoidf_(gi[k] + b_ih[k] + gh[k] + b_hh[k]);
        float z = sigmoidf_(gi[Hd + k] + b_ih[Hd + k] + gh[Hd + k] + b_hh[Hd + k]);
        float nn = tanhf(gi[2 * Hd + k] + b_ih[2 * Hd + k]
                         + r * (gh[2 * Hd + k] + b_hh[2 * Hd + k]));
        float g = (1.f - z) * nn + z * ldh[b * Hd + k];
        out_gru[b * Hd + k] = g;
        gs[k] = g;
    }
    __syncthreads();
    for (int k = warp; k < Hd; k += 8) {
        float a = 0.f;
        #pragma unroll
        for (int t = 0; t < 8; t++) a += gs[lane + 32 * t] * W1[k * Hd + lane + 32 * t];
        #pragma unroll
        for (int o = 16; o; o >>= 1) a += __shfl_xor_sync(0xffffffffu, a, o);
        if (lane == 0) g_h1[b * Hd + k] = fmaxf(a + b1[k], 0.f);
    }
}

// ---------------- BatchNorm stats, parallel (16 blocks) --------------------
__global__ void bn_kernel(const float* __restrict__ gamma, const float* __restrict__ beta) {
    __shared__ float ps[16][16];
    __shared__ float pq[16][16];
    int tid = threadIdx.x;
    int kl = tid & 15, bl = tid >> 4;
    int k = blockIdx.x * 16 + kl;
    float s = 0.f, sq = 0.f;
    #pragma unroll
    for (int j = 0; j < 16; j++) {
        float v = g_h1[(bl + 16 * j) * Hd + k];
        s += v; sq += v * v;
    }
    ps[bl][kl] = s; pq[bl][kl] = sq;
    __syncthreads();
    if (tid < 16) {
        float ts = 0.f, tq = 0.f;
        #pragma unroll
        for (int j = 0; j < 16; j++) { ts += ps[j][tid]; tq += pq[j][tid]; }
        int kk = blockIdx.x * 16 + tid;
        float mu = ts * (1.f / Bd);
        float var = tq * (1.f / Bd) - mu * mu;
        float sc = rsqrtf(var + 1e-5f) * gamma[kk];
        g_scale[kk] = sc; g_shift[kk] = beta[kk] - mu * sc;
    }
}

__global__ void palette_kernel(const float* __restrict__ W2, const float* __restrict__ b2,
                               float* __restrict__ out_pal) {
    int b = blockIdx.x, lane = threadIdx.x & 31, p = threadIdx.x >> 5;
    if (p >= Pd) return;
    float a = 0.f;
    #pragma unroll
    for (int t = 0; t < 8; t++) {
        int h = lane + 32 * t;
        a += (g_h1[b * Hd + h] * g_scale[h] + g_shift[h]) * W2[p * Hd + h];
    }
    #pragma unroll
    for (int o = 16; o; o >>= 1) a += __shfl_xor_sync(0xffffffffu, a, o);
    if (lane == 0) out_pal[b * Pd + p] = a + b2[p];
}

extern "C" void kernel_launch(void* const* d_in, const int* in_sizes, int n_in,
                              void* d_out, int out_size) {
    const float* last_palette = (const float*)d_in[0];
    const float* ldh          = (const float*)d_in[1];
    const float* enc          = (const float*)d_in[2];
    const float* We           = (const float*)d_in[3];
    const float* be           = (const float*)d_in[4];
    const float* Wh           = (const float*)d_in[5];
    const float* bh           = (const float*)d_in[6];
    const float* Wv           = (const float*)d_in[7];
    const float* W_ih         = (const float*)d_in[9];
    const float* b_ih         = (const float*)d_in[10];
    const float* W_hh         = (const float*)d_in[11];
    const float* b_hh         = (const float*)d_in[12];
    const float* W1           = (const float*)d_in[13];
    const float* b1           = (const float*)d_in[14];
    const float* gamma        = (const float*)d_in[15];
    const float* beta         = (const float*)d_in[16];
    const float* W2           = (const float*)d_in[17];
    const float* b2           = (const float*)d_in[18];

    float* out      = (float*)d_out;
    float* out_pal  = out;
    float* out_ctx  = out + Bd * Pd;
    float* out_gru  = out + Bd * Pd + Bd * Hd;
    float* out_attn = out + Bd * Pd + 2 * Bd * Hd;

    static bool attr_done = false;
    if (!attr_done) {
        cudaFuncSetAttribute(energy_hmma_kernel,
                             cudaFuncAttributeMaxDynamicSharedMemorySize, ESMEM);
        attr_done = true;
    }

    hid2_kernel<<<Bd, 256>>>(ldh, Wh, bh, be);
    energy_hmma_kernel<<<NCTAS, 256, ESMEM>>>(enc, We, Wv);
    softmax_kernel<<<Bd, 256>>>(out_attn, out_ctx);
    ctx_part_kernel<<<dim3(Bd, 16), 256>>>(enc, out_attn, out_ctx);
    gru_gemm_kernel<<<96, 256>>>(last_palette, ldh, out_ctx, W_ih, W_hh);
    gru_h1_kernel<<<Bd, 256>>>(ldh, b_ih, b_hh, W1, b1, out_gru);
    bn_kernel<<<16, 256>>>(gamma, beta);
    palette_kernel<<<Bd, 128>>>(W2, b2, out_pal);
}